// round 13
// baseline (speedup 1.0000x reference)
#include <cuda_runtime.h>
#include <cuda_fp16.h>
#include <cstdint>
#include <math.h>

// Problem constants
#define Bb_  2
#define Ss_  2048
#define MEM_ 64
#define Dd_  1024
#define Hh_  16
#define FF_  4096
#define HD_  64
#define NT_  (Bb_ * Ss_)   // 4096 tokens

// -------------------- scratch (device globals; no runtime alloc) --------------------
__device__ float  g_tgt [(size_t)NT_ * Dd_];
__device__ float  g_kvc [(size_t)Bb_ * MEM_ * 2 * Dd_];
__device__ float  g_b2  [2 * Dd_];
__device__ __half g_wTh [(size_t)16 * 1024 * 1024];
__device__ __half g_qkvh[(size_t)NT_ * 3 * Dd_];     // qkv (pre-roped/scaled) / qc
__device__ __half g_xh  [(size_t)NT_ * Dd_];
__device__ __half g_sah [(size_t)NT_ * Dd_];
__device__ __half g_ffnh[(size_t)NT_ * FF_];
__device__ __half g_memh[(size_t)Bb_ * MEM_ * Dd_];

#define WT_QKV 0u
#define WT_O   (3u * 1024u * 1024u)
#define WT_QC  (4u * 1024u * 1024u)
#define WT_KC  (5u * 1024u * 1024u)
#define WT_VC  (6u * 1024u * 1024u)
#define WT_CO  (7u * 1024u * 1024u)
#define WT_W1  (8u * 1024u * 1024u)
#define WT_W2  (12u * 1024u * 1024u)

// -------------------- helpers --------------------
__device__ __forceinline__ uint32_t smem_u32(const void* p) {
    uint32_t a;
    asm("{ .reg .u64 t; cvta.to.shared.u64 t, %1; cvt.u32.u64 %0, t; }" : "=r"(a) : "l"(p));
    return a;
}
__device__ __forceinline__ void cpa16(uint32_t dst, const void* src) {
    asm volatile("cp.async.cg.shared.global [%0], [%1], 16;" :: "r"(dst), "l"(src));
}
__device__ __forceinline__ void ldsm_x4(uint32_t& r0, uint32_t& r1, uint32_t& r2,
                                        uint32_t& r3, uint32_t addr) {
    asm volatile("ldmatrix.sync.aligned.m8n8.x4.shared.b16 {%0,%1,%2,%3}, [%4];"
                 : "=r"(r0), "=r"(r1), "=r"(r2), "=r"(r3) : "r"(addr));
}
__device__ __forceinline__ void ldsm_x4t(uint32_t& r0, uint32_t& r1, uint32_t& r2,
                                         uint32_t& r3, uint32_t addr) {
    asm volatile("ldmatrix.sync.aligned.m8n8.x4.trans.shared.b16 {%0,%1,%2,%3}, [%4];"
                 : "=r"(r0), "=r"(r1), "=r"(r2), "=r"(r3) : "r"(addr));
}
#define CPA_COMMIT() asm volatile("cp.async.commit_group;" ::: "memory")
#define CPA_WAIT1()  asm volatile("cp.async.wait_group 1;"  ::: "memory")
#define CPA_WAIT0()  asm volatile("cp.async.wait_group 0;"  ::: "memory")
#define SWZ(b) ((b) ^ (((b) >> 3) & 0x70))

__device__ __forceinline__ void mma_f16(float* d, uint32_t a0, uint32_t a1, uint32_t a2,
                                        uint32_t a3, uint32_t b0, uint32_t b1) {
    asm volatile(
        "mma.sync.aligned.m16n8k16.row.col.f32.f16.f16.f32 "
        "{%0,%1,%2,%3}, {%4,%5,%6,%7}, {%8,%9}, {%0,%1,%2,%3};"
        : "+f"(d[0]), "+f"(d[1]), "+f"(d[2]), "+f"(d[3])
        : "r"(a0), "r"(a1), "r"(a2), "r"(a3), "r"(b0), "r"(b1));
}
__device__ __forceinline__ uint32_t packh2(float a, float b) {
    __half2 h = __floats2half2_rn(a, b);
    return *reinterpret_cast<uint32_t*>(&h);
}
__device__ __forceinline__ float gelu1(float x) {
    return 0.5f * x * (1.0f + erff(x * 0.7071067811865475f));
}

// -------------------- fused preprocessing --------------------
__global__ void prep_all(const float* __restrict__ W_qkv, const float* __restrict__ W_o,
                         const float* __restrict__ Wq_c, const float* __restrict__ Wk_c,
                         const float* __restrict__ Wv_c, const float* __restrict__ W_co,
                         const float* __restrict__ W1,   const float* __restrict__ W2,
                         const float* __restrict__ memory,
                         const float* __restrict__ bk_c, const float* __restrict__ bv_c)
{
    __shared__ float t[32][33];
    __half* wTh = g_wTh;
    const int bid = blockIdx.x;
    const int tx = threadIdx.x, ty = threadIdx.y;
    const int tid = ty * 32 + tx;

    if (bid < 16384) {
        const float* W; __half* WT; int K, N, lb;
        if (bid < 3072)       { W = W_qkv; WT = wTh + WT_QKV; K = Dd_; N = 3 * Dd_; lb = bid; }
        else if (bid < 4096)  { W = W_o;   WT = wTh + WT_O;   K = Dd_; N = Dd_;     lb = bid - 3072; }
        else if (bid < 5120)  { W = Wq_c;  WT = wTh + WT_QC;  K = Dd_; N = Dd_;     lb = bid - 4096; }
        else if (bid < 6144)  { W = Wk_c;  WT = wTh + WT_KC;  K = Dd_; N = Dd_;     lb = bid - 5120; }
        else if (bid < 7168)  { W = Wv_c;  WT = wTh + WT_VC;  K = Dd_; N = Dd_;     lb = bid - 6144; }
        else if (bid < 8192)  { W = W_co;  WT = wTh + WT_CO;  K = Dd_; N = Dd_;     lb = bid - 7168; }
        else if (bid < 12288) { W = W1;    WT = wTh + WT_W1;  K = Dd_; N = FF_;     lb = bid - 8192; }
        else                  { W = W2;    WT = wTh + WT_W2;  K = FF_; N = Dd_;     lb = bid - 12288; }
        const int nbx = N / 32;
        const int n0 = (lb % nbx) * 32, k0 = (lb / nbx) * 32;
        #pragma unroll
        for (int r = 0; r < 32; r += 8)
            t[ty + r][tx] = W[(size_t)(k0 + ty + r) * N + n0 + tx];
        __syncthreads();
        #pragma unroll
        for (int r = 0; r < 32; r += 8)
            WT[(size_t)(n0 + ty + r) * K + k0 + tx] = __float2half_rn(t[tx][ty + r]);
    } else if (bid < 16896) {
        int i = (bid - 16384) * 256 + tid;
        g_memh[i] = __float2half_rn(memory[i]);
    } else {
        int i = (bid - 16896) * 256 + tid;
        if (i < Dd_) g_b2[i] = bk_c[i];
        else         g_b2[i] = bv_c[i - Dd_];
    }
}

// -------------------- LayerNorm (fp32 in, fp16 out) --------------------
__global__ void layernorm_kernel(const float* __restrict__ x,
                                 const float* __restrict__ g,
                                 const float* __restrict__ be,
                                 __half* __restrict__ y)
{
    int row = blockIdx.x;
    int tid = threadIdx.x;
    const float* xr = x + (size_t)row * Dd_;
    float4 v = *(const float4*)(xr + tid * 4);

    __shared__ float red[8];
    __shared__ float s_mu, s_inv;

    float s = v.x + v.y + v.z + v.w;
    #pragma unroll
    for (int o = 16; o > 0; o >>= 1) s += __shfl_xor_sync(0xffffffffu, s, o);
    if ((tid & 31) == 0) red[tid >> 5] = s;
    __syncthreads();
    if (tid == 0) {
        float t = 0.f;
        #pragma unroll
        for (int i = 0; i < 8; i++) t += red[i];
        s_mu = t * (1.0f / Dd_);
    }
    __syncthreads();
    float mu = s_mu;
    float dx = v.x - mu, dy = v.y - mu, dz = v.z - mu, dw = v.w - mu;
    float q = dx*dx + dy*dy + dz*dz + dw*dw;
    #pragma unroll
    for (int o = 16; o > 0; o >>= 1) q += __shfl_xor_sync(0xffffffffu, q, o);
    if ((tid & 31) == 0) red[tid >> 5] = q;
    __syncthreads();
    if (tid == 0) {
        float t = 0.f;
        #pragma unroll
        for (int i = 0; i < 8; i++) t += red[i];
        s_inv = rsqrtf(t * (1.0f / Dd_) + 1e-5f);
    }
    __syncthreads();
    float inv = s_inv;
    int c = tid * 4;
    __half* yr = y + (size_t)row * Dd_;
    float o0 = dx * inv * g[c + 0] + be[c + 0];
    float o1 = dy * inv * g[c + 1] + be[c + 1];
    float o2 = dz * inv * g[c + 2] + be[c + 2];
    float o3 = dw * inv * g[c + 3] + be[c + 3];
    ((__half2*)(yr + c))[0] = __floats2half2_rn(o0, o1);
    ((__half2*)(yr + c))[1] = __floats2half2_rn(o2, o3);
}

// -------------------- fp16 mma GEMM: CTA 128x128, 3-stage, optional fused RoPE -------
// dorope: for col<2*Dd_ apply RoPE (pair = adjacent cols); col<Dd_ also scale 0.125.
#define GA_STAGE 32768
#define GA_SMEM  (3 * GA_STAGE + 1024)
__global__ __launch_bounds__(256)
void gemm_mma(const __half* __restrict__ A, const __half* __restrict__ WT,
              const float* __restrict__ bias, const float* __restrict__ res,
              float* __restrict__ C, __half* __restrict__ Ch,
              const float* __restrict__ rc, const float* __restrict__ rs,
              int Nc, int Kd, int dogelu, int dorope)
{
    extern __shared__ float dyns[];
    const uint32_t sbase = (smem_u32(dyns) + 1023u) & ~1023u;

    const int tid  = threadIdx.x;
    const int lane = tid & 31, wid = tid >> 5;
    const int gid  = lane >> 2, qd = lane & 3;
    const int wm   = (wid >> 1) * 32;
    const int wn   = (wid & 1) * 64;
    const int n0   = blockIdx.x * 128;
    const int m0   = blockIdx.y * 128;

    const int arow  = wm + (lane & 7) + ((lane >> 3) & 1) * 8;
    const uint32_t acolb = (uint32_t)((lane >> 4) * 16);
    const int bn_base = wn + ((lane >> 4) & 1) * 8 + (lane & 7);
    const uint32_t bcolb = (uint32_t)(((lane >> 3) & 1) * 16);

    float d[2][8][4];
    #pragma unroll
    for (int mt = 0; mt < 2; mt++)
        #pragma unroll
        for (int nt = 0; nt < 8; nt++)
            #pragma unroll
            for (int e = 0; e < 4; e++) d[mt][nt][e] = 0.f;

    const int nsteps = Kd >> 6;
    const __half* Abase = A  + (size_t)m0 * Kd;
    const __half* Bbase = WT + (size_t)n0 * Kd;

    auto cpa_tile = [&](int kstep, int s) {
        const int k0 = kstep * 64;
        const uint32_t aA = sbase + s * GA_STAGE;
        const uint32_t bA = aA + 16384u;
        #pragma unroll
        for (int p = 0; p < 4; p++) {
            int task = p * 256 + tid;
            int r = task >> 3, c = task & 7;
            cpa16(aA + SWZ((uint32_t)(r * 128 + c * 16)), Abase + (size_t)r * Kd + k0 + c * 8);
        }
        #pragma unroll
        for (int p = 0; p < 4; p++) {
            int task = p * 256 + tid;
            int r = task >> 3, c = task & 7;
            cpa16(bA + SWZ((uint32_t)(r * 128 + c * 16)), Bbase + (size_t)r * Kd + k0 + c * 8);
        }
        CPA_COMMIT();
    };

    cpa_tile(0, 0);
    cpa_tile(1, 1);

    for (int i = 0; i < nsteps; i++) {
        const int s = i % 3;
        if (i == nsteps - 1) { CPA_WAIT0(); } else { CPA_WAIT1(); }
        __syncthreads();
        if (i + 2 < nsteps) cpa_tile(i + 2, (i + 2) % 3);

        const uint32_t aA = sbase + s * GA_STAGE;
        const uint32_t bA = aA + 16384u;
        #pragma unroll
        for (int g = 0; g < 4; g++) {
            const uint32_t gb = (uint32_t)(g * 32);
            uint32_t a0[4], a1[4];
            ldsm_x4(a0[0], a0[1], a0[2], a0[3],
                    aA + SWZ((uint32_t)(arow * 128) + gb + acolb));
            ldsm_x4(a1[0], a1[1], a1[2], a1[3],
                    aA + SWZ((uint32_t)((arow + 16) * 128) + gb + acolb));
            uint32_t bf[8][2];
            #pragma unroll
            for (int jp = 0; jp < 4; jp++) {
                int n = bn_base + jp * 16;
                ldsm_x4(bf[jp * 2][0], bf[jp * 2][1], bf[jp * 2 + 1][0], bf[jp * 2 + 1][1],
                        bA + SWZ((uint32_t)(n * 128) + gb + bcolb));
            }
            #pragma unroll
            for (int nt = 0; nt < 8; nt++) {
                mma_f16(d[0][nt], a0[0], a0[1], a0[2], a0[3], bf[nt][0], bf[nt][1]);
                mma_f16(d[1][nt], a1[0], a1[1], a1[2], a1[3], bf[nt][0], bf[nt][1]);
            }
        }
    }

    #pragma unroll
    for (int mt = 0; mt < 2; mt++) {
        #pragma unroll
        for (int nt = 0; nt < 8; nt++) {
            const int r0  = m0 + wm + mt * 16 + gid;
            const int col = n0 + wn + nt * 8 + qd * 2;
            float2 b2 = *(const float2*)(bias + col);
            #pragma unroll
            for (int half_ = 0; half_ < 2; half_++) {
                const int row = r0 + half_ * 8;
                float ox = d[mt][nt][half_ * 2 + 0] + b2.x;
                float oy = d[mt][nt][half_ * 2 + 1] + b2.y;
                if (res) {
                    float2 r2 = *(const float2*)(res + (size_t)row * Nc + col);
                    ox += r2.x; oy += r2.y;
                }
                if (dogelu) { ox = gelu1(ox); oy = gelu1(oy); }
                if (dorope && col < 2 * Dd_) {
                    int pos  = row & (Ss_ - 1);
                    int pidx = (col & 63) >> 1;
                    float c  = rc[pos * 32 + pidx];
                    float sn = rs[pos * 32 + pidx];
                    float re = ox * c - oy * sn;
                    float im = ox * sn + oy * c;
                    if (col < Dd_) { re *= 0.125f; im *= 0.125f; }
                    ox = re; oy = im;
                }
                if (Ch) {
                    *(__half2*)(Ch + (size_t)row * Nc + col) = __floats2half2_rn(ox, oy);
                } else {
                    float2 o2; o2.x = ox; o2.y = oy;
                    *(float2*)(C + (size_t)row * Nc + col) = o2;
                }
            }
        }
    }
}

// -------------------- fp16 mma flash attention, cp.async double-buffered -------------
// qkvh already roped + Q pre-scaled. 1 block = 64 queries x (b,h). 128 thr / 4 warps.
// smem: K0 V0 K1 V1, 8KB each = 32KB.
#define FAH_SMEM 32768
__global__ __launch_bounds__(128)
void flash_attn_h(const __half* __restrict__ qkvh, __half* __restrict__ out)
{
    extern __shared__ __half smh[];
    const uint32_t sb = smem_u32(smh);
    const uint32_t kAs[2] = { sb,          sb + 16384u };
    const uint32_t vAs[2] = { sb + 8192u,  sb + 24576u };

    const int qb = (int)gridDim.x - 1 - (int)blockIdx.x;
    const int q0 = qb * 64;
    const int bh = blockIdx.y;
    const int b = bh >> 4, h = bh & 15;
    const int tid = threadIdx.x, lane = tid & 31, wid = tid >> 5;
    const int gid = lane >> 2, qd = lane & 3;
    const int wr = wid * 16;
    const int rs3 = 3 * Dd_;

    const __half* qbase = qkvh + (size_t)(b * Ss_ + q0) * rs3 + h * HD_;
    const __half* kbase = qkvh + (size_t)(b * Ss_) * rs3 + Dd_ + h * HD_;
    const __half* vbase = qkvh + (size_t)(b * Ss_) * rs3 + 2 * Dd_ + h * HD_;

    // ---- stage Q via cp.async into kAs[0], load A-frags ----
    {
        #pragma unroll
        for (int p = 0; p < 4; p++) {
            int task = p * 128 + tid;
            int r = task >> 3, c = task & 7;
            cpa16(kAs[0] + SWZ((uint32_t)(r * 128 + c * 16)), qbase + (size_t)r * rs3 + c * 8);
        }
        CPA_COMMIT();
        CPA_WAIT0();
        __syncthreads();
    }
    uint32_t qf[4][4];
    {
        const int ar = wr + (lane & 7) + ((lane >> 3) & 1) * 8;
        const uint32_t ac = (uint32_t)((lane >> 4) * 16);
        #pragma unroll
        for (int g = 0; g < 4; g++)
            ldsm_x4(qf[g][0], qf[g][1], qf[g][2], qf[g][3],
                    kAs[0] + SWZ((uint32_t)(ar * 128) + (uint32_t)(g * 32) + ac));
    }
    __syncthreads();

    // KV tile loader (raw copies)
    auto cpa_kv = [&](int t, int s) {
        const int k0 = t * 64;
        #pragma unroll
        for (int p = 0; p < 4; p++) {
            int task = p * 128 + tid;
            int r = task >> 3, c = task & 7;
            cpa16(kAs[s] + SWZ((uint32_t)(r * 128 + c * 16)),
                  kbase + (size_t)(k0 + r) * rs3 + c * 8);
        }
        #pragma unroll
        for (int p = 0; p < 4; p++) {
            int task = p * 128 + tid;
            int r = task >> 3, c = task & 7;
            cpa16(vAs[s] + SWZ((uint32_t)(r * 128 + c * 16)),
                  vbase + (size_t)(k0 + r) * rs3 + c * 8);
        }
        CPA_COMMIT();
    };

    float of[8][4];
    #pragma unroll
    for (int nt = 0; nt < 8; nt++)
        #pragma unroll
        for (int e = 0; e < 4; e++) of[nt][e] = 0.f;
    float m1 = -1e30f, m2 = -1e30f, l1 = 0.f, l2 = 0.f;

    const int aq1 = q0 + wr + gid;
    const int bn_base = ((lane >> 4) & 1) * 8 + (lane & 7);
    const uint32_t bcolb = (uint32_t)(((lane >> 3) & 1) * 16);
    const int vrow_l = (lane & 7) + ((lane >> 3) & 1) * 8;
    const uint32_t vcol_l = (uint32_t)(((lane >> 4) & 1) * 16);

    cpa_kv(0, 0);

    for (int t = 0; t <= qb; t++) {
        const int s = t & 1;
        if (t < qb) { cpa_kv(t + 1, s ^ 1); CPA_WAIT1(); }
        else        { CPA_WAIT0(); }
        __syncthreads();

        const uint32_t kA = kAs[s], vA = vAs[s];
        const int k0 = t * 64;

        // S = Q @ K^T
        float sf[8][4];
        #pragma unroll
        for (int nt = 0; nt < 8; nt++)
            #pragma unroll
            for (int e = 0; e < 4; e++) sf[nt][e] = 0.f;

        #pragma unroll
        for (int g = 0; g < 4; g++) {
            const uint32_t gb = (uint32_t)(g * 32);
            uint32_t kb[8][2];
            #pragma unroll
            for (int jp = 0; jp < 4; jp++) {
                int n = bn_base + jp * 16;
                ldsm_x4(kb[jp * 2][0], kb[jp * 2][1], kb[jp * 2 + 1][0], kb[jp * 2 + 1][1],
                        kA + SWZ((uint32_t)(n * 128) + gb + bcolb));
            }
            #pragma unroll
            for (int nt = 0; nt < 8; nt++)
                mma_f16(sf[nt], qf[g][0], qf[g][1], qf[g][2], qf[g][3], kb[nt][0], kb[nt][1]);
        }

        if (t == qb) {
            #pragma unroll
            for (int nt = 0; nt < 8; nt++) {
                int c = k0 + nt * 8 + qd * 2;
                if (c     > aq1)     sf[nt][0] = -1e30f;
                if (c + 1 > aq1)     sf[nt][1] = -1e30f;
                if (c     > aq1 + 8) sf[nt][2] = -1e30f;
                if (c + 1 > aq1 + 8) sf[nt][3] = -1e30f;
            }
        }

        float mx1 = -1e30f, mx2 = -1e30f;
        #pragma unroll
        for (int nt = 0; nt < 8; nt++) {
            mx1 = fmaxf(mx1, fmaxf(sf[nt][0], sf[nt][1]));
            mx2 = fmaxf(mx2, fmaxf(sf[nt][2], sf[nt][3]));
        }
        mx1 = fmaxf(mx1, __shfl_xor_sync(0xffffffffu, mx1, 1));
        mx1 = fmaxf(mx1, __shfl_xor_sync(0xffffffffu, mx1, 2));
        mx2 = fmaxf(mx2, __shfl_xor_sync(0xffffffffu, mx2, 1));
        mx2 = fmaxf(mx2, __shfl_xor_sync(0xffffffffu, mx2, 2));
        float nm1 = fmaxf(m1, mx1), nm2 = fmaxf(m2, mx2);
        float f1 = __expf(m1 - nm1), f2v = __expf(m2 - nm2);
        m1 = nm1; m2 = nm2;
        float s1 = 0.f, s2 = 0.f;
        #pragma unroll
        for (int nt = 0; nt < 8; nt++) {
            sf[nt][0] = __expf(sf[nt][0] - nm1); s1 += sf[nt][0];
            sf[nt][1] = __expf(sf[nt][1] - nm1); s1 += sf[nt][1];
            sf[nt][2] = __expf(sf[nt][2] - nm2); s2 += sf[nt][2];
            sf[nt][3] = __expf(sf[nt][3] - nm2); s2 += sf[nt][3];
        }
        s1 += __shfl_xor_sync(0xffffffffu, s1, 1);
        s1 += __shfl_xor_sync(0xffffffffu, s1, 2);
        s2 += __shfl_xor_sync(0xffffffffu, s2, 1);
        s2 += __shfl_xor_sync(0xffffffffu, s2, 2);
        l1 = l1 * f1 + s1;
        l2 = l2 * f2v + s2;
        #pragma unroll
        for (int nt = 0; nt < 8; nt++) {
            of[nt][0] *= f1;  of[nt][1] *= f1;
            of[nt][2] *= f2v; of[nt][3] *= f2v;
        }

        #pragma unroll
        for (int g2 = 0; g2 < 4; g2++) {
            uint32_t pa0 = packh2(sf[2 * g2][0], sf[2 * g2][1]);
            uint32_t pa1 = packh2(sf[2 * g2][2], sf[2 * g2][3]);
            uint32_t pa2 = packh2(sf[2 * g2 + 1][0], sf[2 * g2 + 1][1]);
            uint32_t pa3 = packh2(sf[2 * g2 + 1][2], sf[2 * g2 + 1][3]);
            const int vrow = g2 * 16 + vrow_l;
            #pragma unroll
            for (int dp = 0; dp < 4; dp++) {
                uint32_t r0, r1, r2, r3;
                ldsm_x4t(r0, r1, r2, r3,
                         vA + SWZ((uint32_t)(vrow * 128) + (uint32_t)(dp * 32) + vcol_l));
                mma_f16(of[2 * dp],     pa0, pa1, pa2, pa3, r0, r1);
                mma_f16(of[2 * dp + 1], pa0, pa1, pa2, pa3, r2, r3);
            }
        }
        __syncthreads();
    }

    float inv1 = 1.0f / l1, inv2 = 1.0f / l2;
    __half* o1base = out + (size_t)(b * Ss_ + aq1) * Dd_ + h * HD_;
    __half* o2base = out + (size_t)(b * Ss_ + aq1 + 8) * Dd_ + h * HD_;
    #pragma unroll
    for (int nt = 0; nt < 8; nt++) {
        *(__half2*)(o1base + nt * 8 + qd * 2) = __floats2half2_rn(of[nt][0] * inv1, of[nt][1] * inv1);
        *(__half2*)(o2base + nt * 8 + qd * 2) = __floats2half2_rn(of[nt][2] * inv2, of[nt][3] * inv2);
    }
}

// -------------------- Cross-attention (64 keys, fp16 q, kvc fp32 stride 2048) ---------
__global__ __launch_bounds__(64)
void cross_attn_kernel(const __half* __restrict__ qch, const float* __restrict__ kvc,
                       __half* __restrict__ out)
{
    int qidx = blockIdx.x;
    int bh   = blockIdx.y;
    int b = bh / Hh_, h = bh % Hh_;
    int tid = threadIdx.x;

    __shared__ float sq[HD_];
    __shared__ float p[MEM_];
    __shared__ float red[2];

    const __half* qrow = qch + ((size_t)(b * Ss_ + qidx)) * Dd_ + h * HD_;
    sq[tid] = __half2float(qrow[tid]);
    __syncthreads();

    const float* krow = kvc + ((size_t)(b * MEM_ + tid)) * (2 * Dd_) + h * HD_;
    float s = 0.f;
    #pragma unroll
    for (int d = 0; d < HD_; d += 4) {
        float4 k4 = *(const float4*)(krow + d);
        s = fmaf(sq[d + 0], k4.x, s);
        s = fmaf(sq[d + 1], k4.y, s);
        s = fmaf(sq[d + 2], k4.z, s);
        s = fmaf(sq[d + 3], k4.w, s);
    }
    s *= 0.125f;

    float m = s;
    #pragma unroll
    for (int o = 16; o > 0; o >>= 1) m = fmaxf(m, __shfl_xor_sync(0xffffffffu, m, o));
    if ((tid & 31) == 0) red[tid >> 5] = m;
    __syncthreads();
    float gm = fmaxf(red[0], red[1]);
    float pv = expf(s - gm);
    p[tid] = pv;
    float su = pv;
    #pragma unroll
    for (int o = 16; o > 0; o >>= 1) su += __shfl_xor_sync(0xffffffffu, su, o);
    __syncthreads();
    if ((tid & 31) == 0) red[tid >> 5] = su;
    __syncthreads();
    float gl = red[0] + red[1];

    const float* vbase = kvc + ((size_t)(b * MEM_)) * (2 * Dd_) + Dd_ + h * HD_ + tid;
    float a = 0.f;
    #pragma unroll 4
    for (int j = 0; j < MEM_; j++)
        a = fmaf(p[j], vbase[(size_t)j * (2 * Dd_)], a);

    out[((size_t)(b * Ss_ + qidx)) * Dd_ + h * HD_ + tid] = __float2half_rn(a / gl);
}

// -------------------- launch --------------------
extern "C" void kernel_launch(void* const* d_in, const int* in_sizes, int n_in,
                              void* d_out, int out_size)
{
    const float* tgt      = (const float*)d_in[0];
    const float* memory   = (const float*)d_in[1];
    const float* rope_cos = (const float*)d_in[2];
    const float* rope_sin = (const float*)d_in[3];
    const float* W_qkv    = (const float*)d_in[4];
    const float* b_qkv    = (const float*)d_in[5];
    const float* W_o      = (const float*)d_in[6];
    const float* b_o      = (const float*)d_in[7];
    const float* Wq_c     = (const float*)d_in[8];
    const float* bq_c     = (const float*)d_in[9];
    const float* Wk_c     = (const float*)d_in[10];
    const float* bk_c     = (const float*)d_in[11];
    const float* Wv_c     = (const float*)d_in[12];
    const float* bv_c     = (const float*)d_in[13];
    const float* W_co     = (const float*)d_in[14];
    const float* b_co     = (const float*)d_in[15];
    const float* W1       = (const float*)d_in[16];
    const float* b1       = (const float*)d_in[17];
    const float* W2       = (const float*)d_in[18];
    const float* b2       = (const float*)d_in[19];
    const float* g1       = (const float*)d_in[20];
    const float* be1      = (const float*)d_in[21];
    const float* g2       = (const float*)d_in[22];
    const float* be2      = (const float*)d_in[23];
    const float* g3       = (const float*)d_in[24];
    const float* be3      = (const float*)d_in[25];
    float* out = (float*)d_out;

    float *tgtb, *kvc, *b2c;
    __half *wTh, *qkvh, *xh, *sah, *ffnh, *memh;
    cudaGetSymbolAddress((void**)&tgtb, g_tgt);
    cudaGetSymbolAddress((void**)&kvc,  g_kvc);
    cudaGetSymbolAddress((void**)&b2c,  g_b2);
    cudaGetSymbolAddress((void**)&wTh,  g_wTh);
    cudaGetSymbolAddress((void**)&qkvh, g_qkvh);
    cudaGetSymbolAddress((void**)&xh,   g_xh);
    cudaGetSymbolAddress((void**)&sah,  g_sah);
    cudaGetSymbolAddress((void**)&ffnh, g_ffnh);
    cudaGetSymbolAddress((void**)&memh, g_memh);

    cudaFuncSetAttribute(flash_attn_h,
                         cudaFuncAttributeMaxDynamicSharedMemorySize, FAH_SMEM);
    cudaFuncSetAttribute(gemm_mma,
                         cudaFuncAttributeMaxDynamicSharedMemorySize, GA_SMEM);

    // 0) fused preprocessing
    prep_all<<<16904, dim3(32, 8)>>>(W_qkv, W_o, Wq_c, Wk_c, Wv_c, W_co, W1, W2,
                                     memory, bk_c, bv_c);

    // 1) xh = LN1(tgt)
    layernorm_kernel<<<NT_, 256>>>(tgt, g1, be1, xh);
    // 2) qkvh = RoPE(xh @ W_qkv + b) (fp16 out; RoPE+Q-scale fused in epilogue)
    gemm_mma<<<dim3(3 * Dd_ / 128, NT_ / 128), 256, GA_SMEM>>>(
        xh, wTh + WT_QKV, b_qkv, nullptr, nullptr, qkvh, rope_cos, rope_sin, 3 * Dd_, Dd_, 0, 1);
    // 3) causal self-attention (fp16 mma, cp.async double-buffered) -> sah
    flash_attn_h<<<dim3(Ss_ / 64, Bb_ * Hh_), 128, FAH_SMEM>>>(qkvh, sah);
    // 4) tgtb = tgt + sah @ W_o + b_o
    gemm_mma<<<dim3(Dd_ / 128, NT_ / 128), 256, GA_SMEM>>>(
        sah, wTh + WT_O, b_o, tgt, tgtb, nullptr, nullptr, nullptr, Dd_, Dd_, 0, 0);
    // 5) xh = LN2(tgtb)
    layernorm_kernel<<<NT_, 256>>>(tgtb, g2, be2, xh);
    // 6) qch = xh @ Wq_c (fp16 out, into qkvh buffer)
    gemm_mma<<<dim3(Dd_ / 128, NT_ / 128), 256, GA_SMEM>>>(
        xh, wTh + WT_QC, bq_c, nullptr, nullptr, qkvh, nullptr, nullptr, Dd_, Dd_, 0, 0);
    // 7) kvc = memh @ [Wk_c|Wv_c]
    gemm_mma<<<dim3(2 * Dd_ / 128, 1), 256, GA_SMEM>>>(
        memh, wTh + WT_KC, b2c, nullptr, kvc, nullptr, nullptr, nullptr, 2 * Dd_, Dd_, 0, 0);
    // 8) cross-attention -> sah (fp16)
    cross_attn_kernel<<<dim3(Ss_, Bb_ * Hh_), 64>>>(qkvh, kvc, sah);
    // 9) tgtb += sah @ W_co + b_co
    gemm_mma<<<dim3(Dd_ / 128, NT_ / 128), 256, GA_SMEM>>>(
        sah, wTh + WT_CO, b_co, tgtb, tgtb, nullptr, nullptr, nullptr, Dd_, Dd_, 0, 0);
    // 10) xh = LN3(tgtb)
    layernorm_kernel<<<NT_, 256>>>(tgtb, g3, be3, xh);
    // 11) ffnh = gelu(xh @ W1 + b1) (fp16 out)
    gemm_mma<<<dim3(FF_ / 128, NT_ / 128), 256, GA_SMEM>>>(
        xh, wTh + WT_W1, b1, nullptr, nullptr, ffnh, nullptr, nullptr, FF_, Dd_, 1, 0);
    // 12) out = tgtb + ffnh @ W2 + b2
    gemm_mma<<<dim3(Dd_ / 128, NT_ / 128), 256, GA_SMEM>>>(
        ffnh, wTh + WT_W2, b2, tgtb, out, nullptr, nullptr, nullptr, Dd_, FF_, 0, 0);
}

// round 14
// speedup vs baseline: 1.1431x; 1.1431x over previous
#include <cuda_runtime.h>
#include <cuda_fp16.h>
#include <cstdint>
#include <math.h>

// Problem constants
#define Bb_  2
#define Ss_  2048
#define MEM_ 64
#define Dd_  1024
#define Hh_  16
#define FF_  4096
#define HD_  64
#define NT_  (Bb_ * Ss_)   // 4096 tokens

// -------------------- scratch (device globals; no runtime alloc) --------------------
__device__ float  g_tgt [(size_t)NT_ * Dd_];
__device__ float  g_kvc [(size_t)Bb_ * MEM_ * 2 * Dd_];
__device__ float  g_b2  [2 * Dd_];
__device__ __half g_wTh [(size_t)16 * 1024 * 1024];
__device__ __half g_qkvh[(size_t)NT_ * 3 * Dd_];     // qkv (pre-roped/scaled) / qc
__device__ __half g_xh  [(size_t)NT_ * Dd_];
__device__ __half g_sah [(size_t)NT_ * Dd_];
__device__ __half g_ffnh[(size_t)NT_ * FF_];
__device__ __half g_memh[(size_t)Bb_ * MEM_ * Dd_];

#define WT_QKV 0u
#define WT_O   (3u * 1024u * 1024u)
#define WT_QC  (4u * 1024u * 1024u)
#define WT_KC  (5u * 1024u * 1024u)
#define WT_VC  (6u * 1024u * 1024u)
#define WT_CO  (7u * 1024u * 1024u)
#define WT_W1  (8u * 1024u * 1024u)
#define WT_W2  (12u * 1024u * 1024u)

// -------------------- helpers --------------------
__device__ __forceinline__ uint32_t smem_u32(const void* p) {
    uint32_t a;
    asm("{ .reg .u64 t; cvta.to.shared.u64 t, %1; cvt.u32.u64 %0, t; }" : "=r"(a) : "l"(p));
    return a;
}
__device__ __forceinline__ void cpa16(uint32_t dst, const void* src) {
    asm volatile("cp.async.cg.shared.global [%0], [%1], 16;" :: "r"(dst), "l"(src));
}
__device__ __forceinline__ void ldsm_x4(uint32_t& r0, uint32_t& r1, uint32_t& r2,
                                        uint32_t& r3, uint32_t addr) {
    asm volatile("ldmatrix.sync.aligned.m8n8.x4.shared.b16 {%0,%1,%2,%3}, [%4];"
                 : "=r"(r0), "=r"(r1), "=r"(r2), "=r"(r3) : "r"(addr));
}
__device__ __forceinline__ void ldsm_x4t(uint32_t& r0, uint32_t& r1, uint32_t& r2,
                                         uint32_t& r3, uint32_t addr) {
    asm volatile("ldmatrix.sync.aligned.m8n8.x4.trans.shared.b16 {%0,%1,%2,%3}, [%4];"
                 : "=r"(r0), "=r"(r1), "=r"(r2), "=r"(r3) : "r"(addr));
}
#define CPA_COMMIT() asm volatile("cp.async.commit_group;" ::: "memory")
#define CPA_WAIT1()  asm volatile("cp.async.wait_group 1;"  ::: "memory")
#define CPA_WAIT0()  asm volatile("cp.async.wait_group 0;"  ::: "memory")
#define SWZ(b) ((b) ^ (((b) >> 3) & 0x70))

__device__ __forceinline__ void mma_f16(float* d, uint32_t a0, uint32_t a1, uint32_t a2,
                                        uint32_t a3, uint32_t b0, uint32_t b1) {
    asm volatile(
        "mma.sync.aligned.m16n8k16.row.col.f32.f16.f16.f32 "
        "{%0,%1,%2,%3}, {%4,%5,%6,%7}, {%8,%9}, {%0,%1,%2,%3};"
        : "+f"(d[0]), "+f"(d[1]), "+f"(d[2]), "+f"(d[3])
        : "r"(a0), "r"(a1), "r"(a2), "r"(a3), "r"(b0), "r"(b1));
}
__device__ __forceinline__ uint32_t packh2(float a, float b) {
    __half2 h = __floats2half2_rn(a, b);
    return *reinterpret_cast<uint32_t*>(&h);
}
__device__ __forceinline__ float gelu1(float x) {
    return 0.5f * x * (1.0f + erff(x * 0.7071067811865475f));
}

// -------------------- fused preprocessing --------------------
__global__ void prep_all(const float* __restrict__ W_qkv, const float* __restrict__ W_o,
                         const float* __restrict__ Wq_c, const float* __restrict__ Wk_c,
                         const float* __restrict__ Wv_c, const float* __restrict__ W_co,
                         const float* __restrict__ W1,   const float* __restrict__ W2,
                         const float* __restrict__ memory,
                         const float* __restrict__ bk_c, const float* __restrict__ bv_c)
{
    __shared__ float t[32][33];
    __half* wTh = g_wTh;
    const int bid = blockIdx.x;
    const int tx = threadIdx.x, ty = threadIdx.y;
    const int tid = ty * 32 + tx;

    if (bid < 16384) {
        const float* W; __half* WT; int K, N, lb;
        if (bid < 3072)       { W = W_qkv; WT = wTh + WT_QKV; K = Dd_; N = 3 * Dd_; lb = bid; }
        else if (bid < 4096)  { W = W_o;   WT = wTh + WT_O;   K = Dd_; N = Dd_;     lb = bid - 3072; }
        else if (bid < 5120)  { W = Wq_c;  WT = wTh + WT_QC;  K = Dd_; N = Dd_;     lb = bid - 4096; }
        else if (bid < 6144)  { W = Wk_c;  WT = wTh + WT_KC;  K = Dd_; N = Dd_;     lb = bid - 5120; }
        else if (bid < 7168)  { W = Wv_c;  WT = wTh + WT_VC;  K = Dd_; N = Dd_;     lb = bid - 6144; }
        else if (bid < 8192)  { W = W_co;  WT = wTh + WT_CO;  K = Dd_; N = Dd_;     lb = bid - 7168; }
        else if (bid < 12288) { W = W1;    WT = wTh + WT_W1;  K = Dd_; N = FF_;     lb = bid - 8192; }
        else                  { W = W2;    WT = wTh + WT_W2;  K = FF_; N = Dd_;     lb = bid - 12288; }
        const int nbx = N / 32;
        const int n0 = (lb % nbx) * 32, k0 = (lb / nbx) * 32;
        #pragma unroll
        for (int r = 0; r < 32; r += 8)
            t[ty + r][tx] = W[(size_t)(k0 + ty + r) * N + n0 + tx];
        __syncthreads();
        #pragma unroll
        for (int r = 0; r < 32; r += 8)
            WT[(size_t)(n0 + ty + r) * K + k0 + tx] = __float2half_rn(t[tx][ty + r]);
    } else if (bid < 16896) {
        int i = (bid - 16384) * 256 + tid;
        g_memh[i] = __float2half_rn(memory[i]);
    } else {
        int i = (bid - 16896) * 256 + tid;
        if (i < Dd_) g_b2[i] = bk_c[i];
        else         g_b2[i] = bv_c[i - Dd_];
    }
}

// -------------------- LayerNorm (fp32 in, fp16 out) --------------------
__global__ void layernorm_kernel(const float* __restrict__ x,
                                 const float* __restrict__ g,
                                 const float* __restrict__ be,
                                 __half* __restrict__ y)
{
    int row = blockIdx.x;
    int tid = threadIdx.x;
    const float* xr = x + (size_t)row * Dd_;
    float4 v = *(const float4*)(xr + tid * 4);

    __shared__ float red[8];
    __shared__ float s_mu, s_inv;

    float s = v.x + v.y + v.z + v.w;
    #pragma unroll
    for (int o = 16; o > 0; o >>= 1) s += __shfl_xor_sync(0xffffffffu, s, o);
    if ((tid & 31) == 0) red[tid >> 5] = s;
    __syncthreads();
    if (tid == 0) {
        float t = 0.f;
        #pragma unroll
        for (int i = 0; i < 8; i++) t += red[i];
        s_mu = t * (1.0f / Dd_);
    }
    __syncthreads();
    float mu = s_mu;
    float dx = v.x - mu, dy = v.y - mu, dz = v.z - mu, dw = v.w - mu;
    float q = dx*dx + dy*dy + dz*dz + dw*dw;
    #pragma unroll
    for (int o = 16; o > 0; o >>= 1) q += __shfl_xor_sync(0xffffffffu, q, o);
    if ((tid & 31) == 0) red[tid >> 5] = q;
    __syncthreads();
    if (tid == 0) {
        float t = 0.f;
        #pragma unroll
        for (int i = 0; i < 8; i++) t += red[i];
        s_inv = rsqrtf(t * (1.0f / Dd_) + 1e-5f);
    }
    __syncthreads();
    float inv = s_inv;
    int c = tid * 4;
    __half* yr = y + (size_t)row * Dd_;
    float o0 = dx * inv * g[c + 0] + be[c + 0];
    float o1 = dy * inv * g[c + 1] + be[c + 1];
    float o2 = dz * inv * g[c + 2] + be[c + 2];
    float o3 = dw * inv * g[c + 3] + be[c + 3];
    ((__half2*)(yr + c))[0] = __floats2half2_rn(o0, o1);
    ((__half2*)(yr + c))[1] = __floats2half2_rn(o2, o3);
}

// ======== GEMM mainloop macro (shared by gemm_mma and gemm_qkv) =====================
#define GA_STAGE 32768
#define GA_SMEM  (3 * GA_STAGE + 1024)
#define GEMM_PROLOG_AND_MAINLOOP()                                                     \
    extern __shared__ float dyns[];                                                   \
    const uint32_t sbase = (smem_u32(dyns) + 1023u) & ~1023u;                          \
    const int tid  = threadIdx.x;                                                     \
    const int lane = tid & 31, wid = tid >> 5;                                        \
    const int gid  = lane >> 2, qd = lane & 3;                                        \
    const int wm   = (wid >> 1) * 32;                                                 \
    const int wn   = (wid & 1) * 64;                                                  \
    const int n0   = blockIdx.x * 128;                                                \
    const int m0   = blockIdx.y * 128;                                                \
    const int arow  = wm + (lane & 7) + ((lane >> 3) & 1) * 8;                        \
    const uint32_t acolb = (uint32_t)((lane >> 4) * 16);                              \
    const int bn_base = wn + ((lane >> 4) & 1) * 8 + (lane & 7);                      \
    const uint32_t bcolb = (uint32_t)(((lane >> 3) & 1) * 16);                        \
    float d[2][8][4];                                                                 \
    _Pragma("unroll")                                                                 \
    for (int mt = 0; mt < 2; mt++)                                                    \
        _Pragma("unroll")                                                             \
        for (int nt = 0; nt < 8; nt++)                                                \
            _Pragma("unroll")                                                         \
            for (int e = 0; e < 4; e++) d[mt][nt][e] = 0.f;                           \
    const int nsteps = Kd >> 6;                                                       \
    const __half* Abase = A  + (size_t)m0 * Kd;                                       \
    const __half* Bbase = WT + (size_t)n0 * Kd;                                       \
    auto cpa_tile = [&](int kstep, int s) {                                           \
        const int k0 = kstep * 64;                                                    \
        const uint32_t aA = sbase + s * GA_STAGE;                                     \
        const uint32_t bA = aA + 16384u;                                              \
        _Pragma("unroll")                                                             \
        for (int p = 0; p < 4; p++) {                                                 \
            int task = p * 256 + tid;                                                 \
            int r = task >> 3, c = task & 7;                                          \
            cpa16(aA + SWZ((uint32_t)(r * 128 + c * 16)),                             \
                  Abase + (size_t)r * Kd + k0 + c * 8);                               \
        }                                                                             \
        _Pragma("unroll")                                                             \
        for (int p = 0; p < 4; p++) {                                                 \
            int task = p * 256 + tid;                                                 \
            int r = task >> 3, c = task & 7;                                          \
            cpa16(bA + SWZ((uint32_t)(r * 128 + c * 16)),                             \
                  Bbase + (size_t)r * Kd + k0 + c * 8);                               \
        }                                                                             \
        CPA_COMMIT();                                                                 \
    };                                                                                \
    cpa_tile(0, 0);                                                                   \
    cpa_tile(1, 1);                                                                   \
    for (int i = 0; i < nsteps; i++) {                                                \
        const int s = i % 3;                                                          \
        if (i == nsteps - 1) { CPA_WAIT0(); } else { CPA_WAIT1(); }                   \
        __syncthreads();                                                              \
        if (i + 2 < nsteps) cpa_tile(i + 2, (i + 2) % 3);                             \
        const uint32_t aA = sbase + s * GA_STAGE;                                     \
        const uint32_t bA = aA + 16384u;                                              \
        _Pragma("unroll")                                                             \
        for (int g = 0; g < 4; g++) {                                                 \
            const uint32_t gb = (uint32_t)(g * 32);                                   \
            uint32_t a0[4], a1[4];                                                    \
            ldsm_x4(a0[0], a0[1], a0[2], a0[3],                                       \
                    aA + SWZ((uint32_t)(arow * 128) + gb + acolb));                   \
            ldsm_x4(a1[0], a1[1], a1[2], a1[3],                                       \
                    aA + SWZ((uint32_t)((arow + 16) * 128) + gb + acolb));            \
            uint32_t bf[8][2];                                                        \
            _Pragma("unroll")                                                         \
            for (int jp = 0; jp < 4; jp++) {                                          \
                int n = bn_base + jp * 16;                                            \
                ldsm_x4(bf[jp * 2][0], bf[jp * 2][1],                                 \
                        bf[jp * 2 + 1][0], bf[jp * 2 + 1][1],                         \
                        bA + SWZ((uint32_t)(n * 128) + gb + bcolb));                  \
            }                                                                         \
            _Pragma("unroll")                                                         \
            for (int nt = 0; nt < 8; nt++) {                                          \
                mma_f16(d[0][nt], a0[0], a0[1], a0[2], a0[3], bf[nt][0], bf[nt][1]);  \
                mma_f16(d[1][nt], a1[0], a1[1], a1[2], a1[3], bf[nt][0], bf[nt][1]);  \
            }                                                                         \
        }                                                                             \
    }

// ============ GEMM (general): exact R10 signature/body ==============================
__global__ __launch_bounds__(256)
void gemm_mma(const __half* __restrict__ A, const __half* __restrict__ WT,
              const float* __restrict__ bias, const float* __restrict__ res,
              float* __restrict__ C, __half* __restrict__ Ch,
              int Nc, int Kd, int dogelu)
{
    GEMM_PROLOG_AND_MAINLOOP();

    #pragma unroll
    for (int mt = 0; mt < 2; mt++) {
        #pragma unroll
        for (int nt = 0; nt < 8; nt++) {
            const int r0  = m0 + wm + mt * 16 + gid;
            const int col = n0 + wn + nt * 8 + qd * 2;
            float2 b2 = *(const float2*)(bias + col);
            #pragma unroll
            for (int half_ = 0; half_ < 2; half_++) {
                const int row = r0 + half_ * 8;
                float ox = d[mt][nt][half_ * 2 + 0] + b2.x;
                float oy = d[mt][nt][half_ * 2 + 1] + b2.y;
                if (res) {
                    float2 r2 = *(const float2*)(res + (size_t)row * Nc + col);
                    ox += r2.x; oy += r2.y;
                }
                if (dogelu) { ox = gelu1(ox); oy = gelu1(oy); }
                if (Ch) {
                    *(__half2*)(Ch + (size_t)row * Nc + col) = __floats2half2_rn(ox, oy);
                } else {
                    float2 o2; o2.x = ox; o2.y = oy;
                    *(float2*)(C + (size_t)row * Nc + col) = o2;
                }
            }
        }
    }
}

// ============ GEMM (QKV only): RoPE + Q-scale fused epilogue, fp16 out ==============
__global__ __launch_bounds__(256)
void gemm_qkv(const __half* __restrict__ A, const __half* __restrict__ WT,
              const float* __restrict__ bias, __half* __restrict__ Ch,
              const float* __restrict__ rc, const float* __restrict__ rs,
              int Nc, int Kd)
{
    GEMM_PROLOG_AND_MAINLOOP();

    #pragma unroll
    for (int mt = 0; mt < 2; mt++) {
        #pragma unroll
        for (int nt = 0; nt < 8; nt++) {
            const int r0  = m0 + wm + mt * 16 + gid;
            const int col = n0 + wn + nt * 8 + qd * 2;
            float2 b2 = *(const float2*)(bias + col);
            #pragma unroll
            for (int half_ = 0; half_ < 2; half_++) {
                const int row = r0 + half_ * 8;
                float ox = d[mt][nt][half_ * 2 + 0] + b2.x;
                float oy = d[mt][nt][half_ * 2 + 1] + b2.y;
                if (col < 2 * Dd_) {
                    int pos  = row & (Ss_ - 1);
                    int pidx = (col & 63) >> 1;
                    float c  = rc[pos * 32 + pidx];
                    float sn = rs[pos * 32 + pidx];
                    float re = ox * c - oy * sn;
                    float im = ox * sn + oy * c;
                    if (col < Dd_) { re *= 0.125f; im *= 0.125f; }
                    ox = re; oy = im;
                }
                *(__half2*)(Ch + (size_t)row * Nc + col) = __floats2half2_rn(ox, oy);
            }
        }
    }
}

// -------------------- fp16 mma flash attention, cp.async double-buffered -------------
#define FAH_SMEM 32768
__global__ __launch_bounds__(128)
void flash_attn_h(const __half* __restrict__ qkvh, __half* __restrict__ out)
{
    extern __shared__ __half smh[];
    const uint32_t sb = smem_u32(smh);
    const uint32_t kAs[2] = { sb,          sb + 16384u };
    const uint32_t vAs[2] = { sb + 8192u,  sb + 24576u };

    const int qb = (int)gridDim.x - 1 - (int)blockIdx.x;
    const int q0 = qb * 64;
    const int bh = blockIdx.y;
    const int b = bh >> 4, h = bh & 15;
    const int tid = threadIdx.x, lane = tid & 31, wid = tid >> 5;
    const int gid = lane >> 2, qd = lane & 3;
    const int wr = wid * 16;
    const int rs3 = 3 * Dd_;

    const __half* qbase = qkvh + (size_t)(b * Ss_ + q0) * rs3 + h * HD_;
    const __half* kbase = qkvh + (size_t)(b * Ss_) * rs3 + Dd_ + h * HD_;
    const __half* vbase = qkvh + (size_t)(b * Ss_) * rs3 + 2 * Dd_ + h * HD_;

    {
        #pragma unroll
        for (int p = 0; p < 4; p++) {
            int task = p * 128 + tid;
            int r = task >> 3, c = task & 7;
            cpa16(kAs[0] + SWZ((uint32_t)(r * 128 + c * 16)), qbase + (size_t)r * rs3 + c * 8);
        }
        CPA_COMMIT();
        CPA_WAIT0();
        __syncthreads();
    }
    uint32_t qf[4][4];
    {
        const int ar = wr + (lane & 7) + ((lane >> 3) & 1) * 8;
        const uint32_t ac = (uint32_t)((lane >> 4) * 16);
        #pragma unroll
        for (int g = 0; g < 4; g++)
            ldsm_x4(qf[g][0], qf[g][1], qf[g][2], qf[g][3],
                    kAs[0] + SWZ((uint32_t)(ar * 128) + (uint32_t)(g * 32) + ac));
    }
    __syncthreads();

    auto cpa_kv = [&](int t, int s) {
        const int k0 = t * 64;
        #pragma unroll
        for (int p = 0; p < 4; p++) {
            int task = p * 128 + tid;
            int r = task >> 3, c = task & 7;
            cpa16(kAs[s] + SWZ((uint32_t)(r * 128 + c * 16)),
                  kbase + (size_t)(k0 + r) * rs3 + c * 8);
        }
        #pragma unroll
        for (int p = 0; p < 4; p++) {
            int task = p * 128 + tid;
            int r = task >> 3, c = task & 7;
            cpa16(vAs[s] + SWZ((uint32_t)(r * 128 + c * 16)),
                  vbase + (size_t)(k0 + r) * rs3 + c * 8);
        }
        CPA_COMMIT();
    };

    float of[8][4];
    #pragma unroll
    for (int nt = 0; nt < 8; nt++)
        #pragma unroll
        for (int e = 0; e < 4; e++) of[nt][e] = 0.f;
    float m1 = -1e30f, m2 = -1e30f, l1 = 0.f, l2 = 0.f;

    const int aq1 = q0 + wr + gid;
    const int bn_base = ((lane >> 4) & 1) * 8 + (lane & 7);
    const uint32_t bcolb = (uint32_t)(((lane >> 3) & 1) * 16);
    const int vrow_l = (lane & 7) + ((lane >> 3) & 1) * 8;
    const uint32_t vcol_l = (uint32_t)(((lane >> 4) & 1) * 16);

    cpa_kv(0, 0);

    for (int t = 0; t <= qb; t++) {
        const int s = t & 1;
        if (t < qb) { cpa_kv(t + 1, s ^ 1); CPA_WAIT1(); }
        else        { CPA_WAIT0(); }
        __syncthreads();

        const uint32_t kA = kAs[s], vA = vAs[s];
        const int k0 = t * 64;

        float sf[8][4];
        #pragma unroll
        for (int nt = 0; nt < 8; nt++)
            #pragma unroll
            for (int e = 0; e < 4; e++) sf[nt][e] = 0.f;

        #pragma unroll
        for (int g = 0; g < 4; g++) {
            const uint32_t gb = (uint32_t)(g * 32);
            uint32_t kb[8][2];
            #pragma unroll
            for (int jp = 0; jp < 4; jp++) {
                int n = bn_base + jp * 16;
                ldsm_x4(kb[jp * 2][0], kb[jp * 2][1], kb[jp * 2 + 1][0], kb[jp * 2 + 1][1],
                        kA + SWZ((uint32_t)(n * 128) + gb + bcolb));
            }
            #pragma unroll
            for (int nt = 0; nt < 8; nt++)
                mma_f16(sf[nt], qf[g][0], qf[g][1], qf[g][2], qf[g][3], kb[nt][0], kb[nt][1]);
        }

        if (t == qb) {
            #pragma unroll
            for (int nt = 0; nt < 8; nt++) {
                int c = k0 + nt * 8 + qd * 2;
                if (c     > aq1)     sf[nt][0] = -1e30f;
                if (c + 1 > aq1)     sf[nt][1] = -1e30f;
                if (c     > aq1 + 8) sf[nt][2] = -1e30f;
                if (c + 1 > aq1 + 8) sf[nt][3] = -1e30f;
            }
        }

        float mx1 = -1e30f, mx2 = -1e30f;
        #pragma unroll
        for (int nt = 0; nt < 8; nt++) {
            mx1 = fmaxf(mx1, fmaxf(sf[nt][0], sf[nt][1]));
            mx2 = fmaxf(mx2, fmaxf(sf[nt][2], sf[nt][3]));
        }
        mx1 = fmaxf(mx1, __shfl_xor_sync(0xffffffffu, mx1, 1));
        mx1 = fmaxf(mx1, __shfl_xor_sync(0xffffffffu, mx1, 2));
        mx2 = fmaxf(mx2, __shfl_xor_sync(0xffffffffu, mx2, 1));
        mx2 = fmaxf(mx2, __shfl_xor_sync(0xffffffffu, mx2, 2));
        float nm1 = fmaxf(m1, mx1), nm2 = fmaxf(m2, mx2);
        float f1 = __expf(m1 - nm1), f2v = __expf(m2 - nm2);
        m1 = nm1; m2 = nm2;
        float s1 = 0.f, s2 = 0.f;
        #pragma unroll
        for (int nt = 0; nt < 8; nt++) {
            sf[nt][0] = __expf(sf[nt][0] - nm1); s1 += sf[nt][0];
            sf[nt][1] = __expf(sf[nt][1] - nm1); s1 += sf[nt][1];
            sf[nt][2] = __expf(sf[nt][2] - nm2); s2 += sf[nt][2];
            sf[nt][3] = __expf(sf[nt][3] - nm2); s2 += sf[nt][3];
        }
        s1 += __shfl_xor_sync(0xffffffffu, s1, 1);
        s1 += __shfl_xor_sync(0xffffffffu, s1, 2);
        s2 += __shfl_xor_sync(0xffffffffu, s2, 1);
        s2 += __shfl_xor_sync(0xffffffffu, s2, 2);
        l1 = l1 * f1 + s1;
        l2 = l2 * f2v + s2;
        #pragma unroll
        for (int nt = 0; nt < 8; nt++) {
            of[nt][0] *= f1;  of[nt][1] *= f1;
            of[nt][2] *= f2v; of[nt][3] *= f2v;
        }

        #pragma unroll
        for (int g2 = 0; g2 < 4; g2++) {
            uint32_t pa0 = packh2(sf[2 * g2][0], sf[2 * g2][1]);
            uint32_t pa1 = packh2(sf[2 * g2][2], sf[2 * g2][3]);
            uint32_t pa2 = packh2(sf[2 * g2 + 1][0], sf[2 * g2 + 1][1]);
            uint32_t pa3 = packh2(sf[2 * g2 + 1][2], sf[2 * g2 + 1][3]);
            const int vrow = g2 * 16 + vrow_l;
            #pragma unroll
            for (int dp = 0; dp < 4; dp++) {
                uint32_t r0, r1, r2, r3;
                ldsm_x4t(r0, r1, r2, r3,
                         vA + SWZ((uint32_t)(vrow * 128) + (uint32_t)(dp * 32) + vcol_l));
                mma_f16(of[2 * dp],     pa0, pa1, pa2, pa3, r0, r1);
                mma_f16(of[2 * dp + 1], pa0, pa1, pa2, pa3, r2, r3);
            }
        }
        __syncthreads();
    }

    float inv1 = 1.0f / l1, inv2 = 1.0f / l2;
    __half* o1base = out + (size_t)(b * Ss_ + aq1) * Dd_ + h * HD_;
    __half* o2base = out + (size_t)(b * Ss_ + aq1 + 8) * Dd_ + h * HD_;
    #pragma unroll
    for (int nt = 0; nt < 8; nt++) {
        *(__half2*)(o1base + nt * 8 + qd * 2) = __floats2half2_rn(of[nt][0] * inv1, of[nt][1] * inv1);
        *(__half2*)(o2base + nt * 8 + qd * 2) = __floats2half2_rn(of[nt][2] * inv2, of[nt][3] * inv2);
    }
}

// -------------------- Cross-attention --------------------
__global__ __launch_bounds__(64)
void cross_attn_kernel(const __half* __restrict__ qch, const float* __restrict__ kvc,
                       __half* __restrict__ out)
{
    int qidx = blockIdx.x;
    int bh   = blockIdx.y;
    int b = bh / Hh_, h = bh % Hh_;
    int tid = threadIdx.x;

    __shared__ float sq[HD_];
    __shared__ float p[MEM_];
    __shared__ float red[2];

    const __half* qrow = qch + ((size_t)(b * Ss_ + qidx)) * Dd_ + h * HD_;
    sq[tid] = __half2float(qrow[tid]);
    __syncthreads();

    const float* krow = kvc + ((size_t)(b * MEM_ + tid)) * (2 * Dd_) + h * HD_;
    float s = 0.f;
    #pragma unroll
    for (int d = 0; d < HD_; d += 4) {
        float4 k4 = *(const float4*)(krow + d);
        s = fmaf(sq[d + 0], k4.x, s);
        s = fmaf(sq[d + 1], k4.y, s);
        s = fmaf(sq[d + 2], k4.z, s);
        s = fmaf(sq[d + 3], k4.w, s);
    }
    s *= 0.125f;

    float m = s;
    #pragma unroll
    for (int o = 16; o > 0; o >>= 1) m = fmaxf(m, __shfl_xor_sync(0xffffffffu, m, o));
    if ((tid & 31) == 0) red[tid >> 5] = m;
    __syncthreads();
    float gm = fmaxf(red[0], red[1]);
    float pv = expf(s - gm);
    p[tid] = pv;
    float su = pv;
    #pragma unroll
    for (int o = 16; o > 0; o >>= 1) su += __shfl_xor_sync(0xffffffffu, su, o);
    __syncthreads();
    if ((tid & 31) == 0) red[tid >> 5] = su;
    __syncthreads();
    float gl = red[0] + red[1];

    const float* vbase = kvc + ((size_t)(b * MEM_)) * (2 * Dd_) + Dd_ + h * HD_ + tid;
    float a = 0.f;
    #pragma unroll 4
    for (int j = 0; j < MEM_; j++)
        a = fmaf(p[j], vbase[(size_t)j * (2 * Dd_)], a);

    out[((size_t)(b * Ss_ + qidx)) * Dd_ + h * HD_ + tid] = __float2half_rn(a / gl);
}

// -------------------- launch --------------------
extern "C" void kernel_launch(void* const* d_in, const int* in_sizes, int n_in,
                              void* d_out, int out_size)
{
    const float* tgt      = (const float*)d_in[0];
    const float* memory   = (const float*)d_in[1];
    const float* rope_cos = (const float*)d_in[2];
    const float* rope_sin = (const float*)d_in[3];
    const float* W_qkv    = (const float*)d_in[4];
    const float* b_qkv    = (const float*)d_in[5];
    const float* W_o      = (const float*)d_in[6];
    const float* b_o      = (const float*)d_in[7];
    const float* Wq_c     = (const float*)d_in[8];
    const float* bq_c     = (const float*)d_in[9];
    const float* Wk_c     = (const float*)d_in[10];
    const float* bk_c     = (const float*)d_in[11];
    const float* Wv_c     = (const float*)d_in[12];
    const float* bv_c     = (const float*)d_in[13];
    const float* W_co     = (const float*)d_in[14];
    const float* b_co     = (const float*)d_in[15];
    const float* W1       = (const float*)d_in[16];
    const float* b1       = (const float*)d_in[17];
    const float* W2       = (const float*)d_in[18];
    const float* b2       = (const float*)d_in[19];
    const float* g1       = (const float*)d_in[20];
    const float* be1      = (const float*)d_in[21];
    const float* g2       = (const float*)d_in[22];
    const float* be2      = (const float*)d_in[23];
    const float* g3       = (const float*)d_in[24];
    const float* be3      = (const float*)d_in[25];
    float* out = (float*)d_out;

    float *tgtb, *kvc, *b2c;
    __half *wTh, *qkvh, *xh, *sah, *ffnh, *memh;
    cudaGetSymbolAddress((void**)&tgtb, g_tgt);
    cudaGetSymbolAddress((void**)&kvc,  g_kvc);
    cudaGetSymbolAddress((void**)&b2c,  g_b2);
    cudaGetSymbolAddress((void**)&wTh,  g_wTh);
    cudaGetSymbolAddress((void**)&qkvh, g_qkvh);
    cudaGetSymbolAddress((void**)&xh,   g_xh);
    cudaGetSymbolAddress((void**)&sah,  g_sah);
    cudaGetSymbolAddress((void**)&ffnh, g_ffnh);
    cudaGetSymbolAddress((void**)&memh, g_memh);

    cudaFuncSetAttribute(flash_attn_h,
                         cudaFuncAttributeMaxDynamicSharedMemorySize, FAH_SMEM);
    cudaFuncSetAttribute(gemm_mma,
                         cudaFuncAttributeMaxDynamicSharedMemorySize, GA_SMEM);
    cudaFuncSetAttribute(gemm_qkv,
                         cudaFuncAttributeMaxDynamicSharedMemorySize, GA_SMEM);

    // 0) fused preprocessing
    prep_all<<<16904, dim3(32, 8)>>>(W_qkv, W_o, Wq_c, Wk_c, Wv_c, W_co, W1, W2,
                                     memory, bk_c, bv_c);

    // 1) xh = LN1(tgt)
    layernorm_kernel<<<NT_, 256>>>(tgt, g1, be1, xh);
    // 2) qkvh = RoPE(xh @ W_qkv + b) (dedicated kernel)
    gemm_qkv<<<dim3(3 * Dd_ / 128, NT_ / 128), 256, GA_SMEM>>>(
        xh, wTh + WT_QKV, b_qkv, qkvh, rope_cos, rope_sin, 3 * Dd_, Dd_);
    // 3) causal self-attention -> sah
    flash_attn_h<<<dim3(Ss_ / 64, Bb_ * Hh_), 128, FAH_SMEM>>>(qkvh, sah);
    // 4) tgtb = tgt + sah @ W_o + b_o
    gemm_mma<<<dim3(Dd_ / 128, NT_ / 128), 256, GA_SMEM>>>(
        sah, wTh + WT_O, b_o, tgt, tgtb, nullptr, Dd_, Dd_, 0);
    // 5) xh = LN2(tgtb)
    layernorm_kernel<<<NT_, 256>>>(tgtb, g2, be2, xh);
    // 6) qch = xh @ Wq_c (fp16 out)
    gemm_mma<<<dim3(Dd_ / 128, NT_ / 128), 256, GA_SMEM>>>(
        xh, wTh + WT_QC, bq_c, nullptr, nullptr, qkvh, Dd_, Dd_, 0);
    // 7) kvc = memh @ [Wk_c|Wv_c]
    gemm_mma<<<dim3(2 * Dd_ / 128, 1), 256, GA_SMEM>>>(
        memh, wTh + WT_KC, b2c, nullptr, kvc, nullptr, 2 * Dd_, Dd_, 0);
    // 8) cross-attention -> sah
    cross_attn_kernel<<<dim3(Ss_, Bb_ * Hh_), 64>>>(qkvh, kvc, sah);
    // 9) tgtb += sah @ W_co + b_co
    gemm_mma<<<dim3(Dd_ / 128, NT_ / 128), 256, GA_SMEM>>>(
        sah, wTh + WT_CO, b_co, tgtb, tgtb, nullptr, Dd_, Dd_, 0);
    // 10) xh = LN3(tgtb)
    layernorm_kernel<<<NT_, 256>>>(tgtb, g3, be3, xh);
    // 11) ffnh = gelu(xh @ W1 + b1)
    gemm_mma<<<dim3(FF_ / 128, NT_ / 128), 256, GA_SMEM>>>(
        xh, wTh + WT_W1, b1, nullptr, nullptr, ffnh, FF_, Dd_, 1);
    // 12) out = tgtb + ffnh @ W2 + b2
    gemm_mma<<<dim3(Dd_ / 128, NT_ / 128), 256, GA_SMEM>>>(
        ffnh, wTh + WT_W2, b2, tgtb, out, nullptr, Dd_, FF_, 0);
}

// round 15
// speedup vs baseline: 1.1453x; 1.0019x over previous
#include <cuda_runtime.h>
#include <cuda_fp16.h>
#include <cstdint>
#include <math.h>

// Problem constants
#define Bb_  2
#define Ss_  2048
#define MEM_ 64
#define Dd_  1024
#define Hh_  16
#define FF_  4096
#define HD_  64
#define NT_  (Bb_ * Ss_)   // 4096 tokens

// -------------------- scratch (device globals; no runtime alloc) --------------------
__device__ float  g_tgt [(size_t)NT_ * Dd_];
__device__ float  g_kvc [(size_t)Bb_ * MEM_ * 2 * Dd_];
__device__ float  g_b2  [2 * Dd_];
__device__ __half g_wTh [(size_t)16 * 1024 * 1024];
__device__ __half g_qkvh[(size_t)NT_ * 3 * Dd_];     // qkv (pre-roped/scaled) / qc
__device__ __half g_xh  [(size_t)NT_ * Dd_];
__device__ __half g_sah [(size_t)NT_ * Dd_];
__device__ __half g_ffnh[(size_t)NT_ * FF_];
__device__ __half g_memh[(size_t)Bb_ * MEM_ * Dd_];

#define WT_QKV 0u
#define WT_O   (3u * 1024u * 1024u)
#define WT_QC  (4u * 1024u * 1024u)
#define WT_KC  (5u * 1024u * 1024u)
#define WT_VC  (6u * 1024u * 1024u)
#define WT_CO  (7u * 1024u * 1024u)
#define WT_W1  (8u * 1024u * 1024u)
#define WT_W2  (12u * 1024u * 1024u)

// -------------------- helpers --------------------
__device__ __forceinline__ uint32_t smem_u32(const void* p) {
    uint32_t a;
    asm("{ .reg .u64 t; cvta.to.shared.u64 t, %1; cvt.u32.u64 %0, t; }" : "=r"(a) : "l"(p));
    return a;
}
__device__ __forceinline__ void cpa16(uint32_t dst, const void* src) {
    asm volatile("cp.async.cg.shared.global [%0], [%1], 16;" :: "r"(dst), "l"(src));
}
__device__ __forceinline__ void ldsm_x4(uint32_t& r0, uint32_t& r1, uint32_t& r2,
                                        uint32_t& r3, uint32_t addr) {
    asm volatile("ldmatrix.sync.aligned.m8n8.x4.shared.b16 {%0,%1,%2,%3}, [%4];"
                 : "=r"(r0), "=r"(r1), "=r"(r2), "=r"(r3) : "r"(addr));
}
__device__ __forceinline__ void ldsm_x4t(uint32_t& r0, uint32_t& r1, uint32_t& r2,
                                         uint32_t& r3, uint32_t addr) {
    asm volatile("ldmatrix.sync.aligned.m8n8.x4.trans.shared.b16 {%0,%1,%2,%3}, [%4];"
                 : "=r"(r0), "=r"(r1), "=r"(r2), "=r"(r3) : "r"(addr));
}
#define CPA_COMMIT() asm volatile("cp.async.commit_group;" ::: "memory")
#define CPA_WAIT1()  asm volatile("cp.async.wait_group 1;"  ::: "memory")
#define CPA_WAIT0()  asm volatile("cp.async.wait_group 0;"  ::: "memory")
#define SWZ(b) ((b) ^ (((b) >> 3) & 0x70))

__device__ __forceinline__ void mma_f16(float* d, uint32_t a0, uint32_t a1, uint32_t a2,
                                        uint32_t a3, uint32_t b0, uint32_t b1) {
    asm volatile(
        "mma.sync.aligned.m16n8k16.row.col.f32.f16.f16.f32 "
        "{%0,%1,%2,%3}, {%4,%5,%6,%7}, {%8,%9}, {%0,%1,%2,%3};"
        : "+f"(d[0]), "+f"(d[1]), "+f"(d[2]), "+f"(d[3])
        : "r"(a0), "r"(a1), "r"(a2), "r"(a3), "r"(b0), "r"(b1));
}
__device__ __forceinline__ uint32_t packh2(float a, float b) {
    __half2 h = __floats2half2_rn(a, b);
    return *reinterpret_cast<uint32_t*>(&h);
}
__device__ __forceinline__ float gelu1(float x) {
    return 0.5f * x * (1.0f + erff(x * 0.7071067811865475f));
}

// -------------------- fused preprocessing --------------------
__global__ void prep_all(const float* __restrict__ W_qkv, const float* __restrict__ W_o,
                         const float* __restrict__ Wq_c, const float* __restrict__ Wk_c,
                         const float* __restrict__ Wv_c, const float* __restrict__ W_co,
                         const float* __restrict__ W1,   const float* __restrict__ W2,
                         const float* __restrict__ memory,
                         const float* __restrict__ bk_c, const float* __restrict__ bv_c)
{
    __shared__ float t[32][33];
    __half* wTh = g_wTh;
    const int bid = blockIdx.x;
    const int tx = threadIdx.x, ty = threadIdx.y;
    const int tid = ty * 32 + tx;

    if (bid < 16384) {
        const float* W; __half* WT; int K, N, lb;
        if (bid < 3072)       { W = W_qkv; WT = wTh + WT_QKV; K = Dd_; N = 3 * Dd_; lb = bid; }
        else if (bid < 4096)  { W = W_o;   WT = wTh + WT_O;   K = Dd_; N = Dd_;     lb = bid - 3072; }
        else if (bid < 5120)  { W = Wq_c;  WT = wTh + WT_QC;  K = Dd_; N = Dd_;     lb = bid - 4096; }
        else if (bid < 6144)  { W = Wk_c;  WT = wTh + WT_KC;  K = Dd_; N = Dd_;     lb = bid - 5120; }
        else if (bid < 7168)  { W = Wv_c;  WT = wTh + WT_VC;  K = Dd_; N = Dd_;     lb = bid - 6144; }
        else if (bid < 8192)  { W = W_co;  WT = wTh + WT_CO;  K = Dd_; N = Dd_;     lb = bid - 7168; }
        else if (bid < 12288) { W = W1;    WT = wTh + WT_W1;  K = Dd_; N = FF_;     lb = bid - 8192; }
        else                  { W = W2;    WT = wTh + WT_W2;  K = FF_; N = Dd_;     lb = bid - 12288; }
        const int nbx = N / 32;
        const int n0 = (lb % nbx) * 32, k0 = (lb / nbx) * 32;
        #pragma unroll
        for (int r = 0; r < 32; r += 8)
            t[ty + r][tx] = W[(size_t)(k0 + ty + r) * N + n0 + tx];
        __syncthreads();
        #pragma unroll
        for (int r = 0; r < 32; r += 8)
            WT[(size_t)(n0 + ty + r) * K + k0 + tx] = __float2half_rn(t[tx][ty + r]);
    } else if (bid < 16896) {
        int i = (bid - 16384) * 256 + tid;
        g_memh[i] = __float2half_rn(memory[i]);
    } else {
        int i = (bid - 16896) * 256 + tid;
        if (i < Dd_) g_b2[i] = bk_c[i];
        else         g_b2[i] = bv_c[i - Dd_];
    }
}

// -------------------- LayerNorm (fp32 in, fp16 out) --------------------
__global__ void layernorm_kernel(const float* __restrict__ x,
                                 const float* __restrict__ g,
                                 const float* __restrict__ be,
                                 __half* __restrict__ y)
{
    int row = blockIdx.x;
    int tid = threadIdx.x;
    const float* xr = x + (size_t)row * Dd_;
    float4 v = *(const float4*)(xr + tid * 4);

    __shared__ float red[8];
    __shared__ float s_mu, s_inv;

    float s = v.x + v.y + v.z + v.w;
    #pragma unroll
    for (int o = 16; o > 0; o >>= 1) s += __shfl_xor_sync(0xffffffffu, s, o);
    if ((tid & 31) == 0) red[tid >> 5] = s;
    __syncthreads();
    if (tid == 0) {
        float t = 0.f;
        #pragma unroll
        for (int i = 0; i < 8; i++) t += red[i];
        s_mu = t * (1.0f / Dd_);
    }
    __syncthreads();
    float mu = s_mu;
    float dx = v.x - mu, dy = v.y - mu, dz = v.z - mu, dw = v.w - mu;
    float q = dx*dx + dy*dy + dz*dz + dw*dw;
    #pragma unroll
    for (int o = 16; o > 0; o >>= 1) q += __shfl_xor_sync(0xffffffffu, q, o);
    if ((tid & 31) == 0) red[tid >> 5] = q;
    __syncthreads();
    if (tid == 0) {
        float t = 0.f;
        #pragma unroll
        for (int i = 0; i < 8; i++) t += red[i];
        s_inv = rsqrtf(t * (1.0f / Dd_) + 1e-5f);
    }
    __syncthreads();
    float inv = s_inv;
    int c = tid * 4;
    __half* yr = y + (size_t)row * Dd_;
    float o0 = dx * inv * g[c + 0] + be[c + 0];
    float o1 = dy * inv * g[c + 1] + be[c + 1];
    float o2 = dz * inv * g[c + 2] + be[c + 2];
    float o3 = dw * inv * g[c + 3] + be[c + 3];
    ((__half2*)(yr + c))[0] = __floats2half2_rn(o0, o1);
    ((__half2*)(yr + c))[1] = __floats2half2_rn(o2, o3);
}

// ======== GEMM mainloop macro: CTA 128x128, 128 threads, 4 warps 64x64, 3-stage =====
#define GA_STAGE 32768
#define GA_SMEM  (3 * GA_STAGE + 1024)
#define GEMM_PROLOG_AND_MAINLOOP()                                                     \
    extern __shared__ float dyns[];                                                   \
    const uint32_t sbase = (smem_u32(dyns) + 1023u) & ~1023u;                          \
    const int tid  = threadIdx.x;                                                     \
    const int lane = tid & 31, wid = tid >> 5;                                        \
    const int gid  = lane >> 2, qd = lane & 3;                                        \
    const int wm   = (wid >> 1) * 64;                                                 \
    const int wn   = (wid & 1) * 64;                                                  \
    const int n0   = blockIdx.x * 128;                                                \
    const int m0   = blockIdx.y * 128;                                                \
    const int arow  = wm + (lane & 7) + ((lane >> 3) & 1) * 8;                        \
    const uint32_t acolb = (uint32_t)((lane >> 4) * 16);                              \
    const int bn_base = wn + ((lane >> 4) & 1) * 8 + (lane & 7);                      \
    const uint32_t bcolb = (uint32_t)(((lane >> 3) & 1) * 16);                        \
    float d[4][8][4];                                                                 \
    _Pragma("unroll")                                                                 \
    for (int mt = 0; mt < 4; mt++)                                                    \
        _Pragma("unroll")                                                             \
        for (int nt = 0; nt < 8; nt++)                                                \
            _Pragma("unroll")                                                         \
            for (int e = 0; e < 4; e++) d[mt][nt][e] = 0.f;                           \
    const int nsteps = Kd >> 6;                                                       \
    const __half* Abase = A  + (size_t)m0 * Kd;                                       \
    const __half* Bbase = WT + (size_t)n0 * Kd;                                       \
    auto cpa_tile = [&](int kstep, int s) {                                           \
        const int k0 = kstep * 64;                                                    \
        const uint32_t aA = sbase + s * GA_STAGE;                                     \
        const uint32_t bA = aA + 16384u;                                              \
        _Pragma("unroll")                                                             \
        for (int p = 0; p < 8; p++) {                                                 \
            int task = p * 128 + tid;                                                 \
            int r = task >> 3, c = task & 7;                                          \
            cpa16(aA + SWZ((uint32_t)(r * 128 + c * 16)),                             \
                  Abase + (size_t)r * Kd + k0 + c * 8);                               \
        }                                                                             \
        _Pragma("unroll")                                                             \
        for (int p = 0; p < 8; p++) {                                                 \
            int task = p * 128 + tid;                                                 \
            int r = task >> 3, c = task & 7;                                          \
            cpa16(bA + SWZ((uint32_t)(r * 128 + c * 16)),                             \
                  Bbase + (size_t)r * Kd + k0 + c * 8);                               \
        }                                                                             \
        CPA_COMMIT();                                                                 \
    };                                                                                \
    cpa_tile(0, 0);                                                                   \
    cpa_tile(1, 1);                                                                   \
    for (int i = 0; i < nsteps; i++) {                                                \
        const int s = i % 3;                                                          \
        if (i == nsteps - 1) { CPA_WAIT0(); } else { CPA_WAIT1(); }                   \
        __syncthreads();                                                              \
        if (i + 2 < nsteps) cpa_tile(i + 2, (i + 2) % 3);                             \
        const uint32_t aA = sbase + s * GA_STAGE;                                     \
        const uint32_t bA = aA + 16384u;                                              \
        _Pragma("unroll")                                                             \
        for (int g = 0; g < 4; g++) {                                                 \
            const uint32_t gb = (uint32_t)(g * 32);                                   \
            uint32_t am[4][4];                                                        \
            _Pragma("unroll")                                                         \
            for (int mt = 0; mt < 4; mt++)                                            \
                ldsm_x4(am[mt][0], am[mt][1], am[mt][2], am[mt][3],                   \
                        aA + SWZ((uint32_t)((arow + mt * 16) * 128) + gb + acolb));   \
            uint32_t bf[8][2];                                                        \
            _Pragma("unroll")                                                         \
            for (int jp = 0; jp < 4; jp++) {                                          \
                int n = bn_base + jp * 16;                                            \
                ldsm_x4(bf[jp * 2][0], bf[jp * 2][1],                                 \
                        bf[jp * 2 + 1][0], bf[jp * 2 + 1][1],                         \
                        bA + SWZ((uint32_t)(n * 128) + gb + bcolb));                  \
            }                                                                         \
            _Pragma("unroll")                                                         \
            for (int mt = 0; mt < 4; mt++)                                            \
                _Pragma("unroll")                                                     \
                for (int nt = 0; nt < 8; nt++)                                        \
                    mma_f16(d[mt][nt], am[mt][0], am[mt][1], am[mt][2], am[mt][3],    \
                            bf[nt][0], bf[nt][1]);                                    \
        }                                                                             \
    }

// ============ GEMM (general) ==============================
__global__ __launch_bounds__(128)
void gemm_mma(const __half* __restrict__ A, const __half* __restrict__ WT,
              const float* __restrict__ bias, const float* __restrict__ res,
              float* __restrict__ C, __half* __restrict__ Ch,
              int Nc, int Kd, int dogelu)
{
    GEMM_PROLOG_AND_MAINLOOP();

    #pragma unroll
    for (int mt = 0; mt < 4; mt++) {
        #pragma unroll
        for (int nt = 0; nt < 8; nt++) {
            const int r0  = m0 + wm + mt * 16 + gid;
            const int col = n0 + wn + nt * 8 + qd * 2;
            float2 b2 = *(const float2*)(bias + col);
            #pragma unroll
            for (int half_ = 0; half_ < 2; half_++) {
                const int row = r0 + half_ * 8;
                float ox = d[mt][nt][half_ * 2 + 0] + b2.x;
                float oy = d[mt][nt][half_ * 2 + 1] + b2.y;
                if (res) {
                    float2 r2 = *(const float2*)(res + (size_t)row * Nc + col);
                    ox += r2.x; oy += r2.y;
                }
                if (dogelu) { ox = gelu1(ox); oy = gelu1(oy); }
                if (Ch) {
                    *(__half2*)(Ch + (size_t)row * Nc + col) = __floats2half2_rn(ox, oy);
                } else {
                    float2 o2; o2.x = ox; o2.y = oy;
                    *(float2*)(C + (size_t)row * Nc + col) = o2;
                }
            }
        }
    }
}

// ============ GEMM (QKV only): RoPE + Q-scale fused epilogue, fp16 out ==============
__global__ __launch_bounds__(128)
void gemm_qkv(const __half* __restrict__ A, const __half* __restrict__ WT,
              const float* __restrict__ bias, __half* __restrict__ Ch,
              const float* __restrict__ rc, const float* __restrict__ rs,
              int Nc, int Kd)
{
    GEMM_PROLOG_AND_MAINLOOP();

    #pragma unroll
    for (int mt = 0; mt < 4; mt++) {
        #pragma unroll
        for (int nt = 0; nt < 8; nt++) {
            const int r0  = m0 + wm + mt * 16 + gid;
            const int col = n0 + wn + nt * 8 + qd * 2;
            float2 b2 = *(const float2*)(bias + col);
            #pragma unroll
            for (int half_ = 0; half_ < 2; half_++) {
                const int row = r0 + half_ * 8;
                float ox = d[mt][nt][half_ * 2 + 0] + b2.x;
                float oy = d[mt][nt][half_ * 2 + 1] + b2.y;
                if (col < 2 * Dd_) {
                    int pos  = row & (Ss_ - 1);
                    int pidx = (col & 63) >> 1;
                    float c  = rc[pos * 32 + pidx];
                    float sn = rs[pos * 32 + pidx];
                    float re = ox * c - oy * sn;
                    float im = ox * sn + oy * c;
                    if (col < Dd_) { re *= 0.125f; im *= 0.125f; }
                    ox = re; oy = im;
                }
                *(__half2*)(Ch + (size_t)row * Nc + col) = __floats2half2_rn(ox, oy);
            }
        }
    }
}

// -------------------- fp16 mma flash attention, cp.async double-buffered -------------
#define FAH_SMEM 32768
__global__ __launch_bounds__(128)
void flash_attn_h(const __half* __restrict__ qkvh, __half* __restrict__ out)
{
    extern __shared__ __half smh[];
    const uint32_t sb = smem_u32(smh);
    const uint32_t kAs[2] = { sb,          sb + 16384u };
    const uint32_t vAs[2] = { sb + 8192u,  sb + 24576u };

    const int qb = (int)gridDim.x - 1 - (int)blockIdx.x;
    const int q0 = qb * 64;
    const int bh = blockIdx.y;
    const int b = bh >> 4, h = bh & 15;
    const int tid = threadIdx.x, lane = tid & 31, wid = tid >> 5;
    const int gid = lane >> 2, qd = lane & 3;
    const int wr = wid * 16;
    const int rs3 = 3 * Dd_;

    const __half* qbase = qkvh + (size_t)(b * Ss_ + q0) * rs3 + h * HD_;
    const __half* kbase = qkvh + (size_t)(b * Ss_) * rs3 + Dd_ + h * HD_;
    const __half* vbase = qkvh + (size_t)(b * Ss_) * rs3 + 2 * Dd_ + h * HD_;

    {
        #pragma unroll
        for (int p = 0; p < 4; p++) {
            int task = p * 128 + tid;
            int r = task >> 3, c = task & 7;
            cpa16(kAs[0] + SWZ((uint32_t)(r * 128 + c * 16)), qbase + (size_t)r * rs3 + c * 8);
        }
        CPA_COMMIT();
        CPA_WAIT0();
        __syncthreads();
    }
    uint32_t qf[4][4];
    {
        const int ar = wr + (lane & 7) + ((lane >> 3) & 1) * 8;
        const uint32_t ac = (uint32_t)((lane >> 4) * 16);
        #pragma unroll
        for (int g = 0; g < 4; g++)
            ldsm_x4(qf[g][0], qf[g][1], qf[g][2], qf[g][3],
                    kAs[0] + SWZ((uint32_t)(ar * 128) + (uint32_t)(g * 32) + ac));
    }
    __syncthreads();

    auto cpa_kv = [&](int t, int s) {
        const int k0 = t * 64;
        #pragma unroll
        for (int p = 0; p < 4; p++) {
            int task = p * 128 + tid;
            int r = task >> 3, c = task & 7;
            cpa16(kAs[s] + SWZ((uint32_t)(r * 128 + c * 16)),
                  kbase + (size_t)(k0 + r) * rs3 + c * 8);
        }
        #pragma unroll
        for (int p = 0; p < 4; p++) {
            int task = p * 128 + tid;
            int r = task >> 3, c = task & 7;
            cpa16(vAs[s] + SWZ((uint32_t)(r * 128 + c * 16)),
                  vbase + (size_t)(k0 + r) * rs3 + c * 8);
        }
        CPA_COMMIT();
    };

    float of[8][4];
    #pragma unroll
    for (int nt = 0; nt < 8; nt++)
        #pragma unroll
        for (int e = 0; e < 4; e++) of[nt][e] = 0.f;
    float m1 = -1e30f, m2 = -1e30f, l1 = 0.f, l2 = 0.f;

    const int aq1 = q0 + wr + gid;
    const int bn_base = ((lane >> 4) & 1) * 8 + (lane & 7);
    const uint32_t bcolb = (uint32_t)(((lane >> 3) & 1) * 16);
    const int vrow_l = (lane & 7) + ((lane >> 3) & 1) * 8;
    const uint32_t vcol_l = (uint32_t)(((lane >> 4) & 1) * 16);

    cpa_kv(0, 0);

    for (int t = 0; t <= qb; t++) {
        const int s = t & 1;
        if (t < qb) { cpa_kv(t + 1, s ^ 1); CPA_WAIT1(); }
        else        { CPA_WAIT0(); }
        __syncthreads();

        const uint32_t kA = kAs[s], vA = vAs[s];
        const int k0 = t * 64;

        float sf[8][4];
        #pragma unroll
        for (int nt = 0; nt < 8; nt++)
            #pragma unroll
            for (int e = 0; e < 4; e++) sf[nt][e] = 0.f;

        #pragma unroll
        for (int g = 0; g < 4; g++) {
            const uint32_t gb = (uint32_t)(g * 32);
            uint32_t kb[8][2];
            #pragma unroll
            for (int jp = 0; jp < 4; jp++) {
                int n = bn_base + jp * 16;
                ldsm_x4(kb[jp * 2][0], kb[jp * 2][1], kb[jp * 2 + 1][0], kb[jp * 2 + 1][1],
                        kA + SWZ((uint32_t)(n * 128) + gb + bcolb));
            }
            #pragma unroll
            for (int nt = 0; nt < 8; nt++)
                mma_f16(sf[nt], qf[g][0], qf[g][1], qf[g][2], qf[g][3], kb[nt][0], kb[nt][1]);
        }

        if (t == qb) {
            #pragma unroll
            for (int nt = 0; nt < 8; nt++) {
                int c = k0 + nt * 8 + qd * 2;
                if (c     > aq1)     sf[nt][0] = -1e30f;
                if (c + 1 > aq1)     sf[nt][1] = -1e30f;
                if (c     > aq1 + 8) sf[nt][2] = -1e30f;
                if (c + 1 > aq1 + 8) sf[nt][3] = -1e30f;
            }
        }

        float mx1 = -1e30f, mx2 = -1e30f;
        #pragma unroll
        for (int nt = 0; nt < 8; nt++) {
            mx1 = fmaxf(mx1, fmaxf(sf[nt][0], sf[nt][1]));
            mx2 = fmaxf(mx2, fmaxf(sf[nt][2], sf[nt][3]));
        }
        mx1 = fmaxf(mx1, __shfl_xor_sync(0xffffffffu, mx1, 1));
        mx1 = fmaxf(mx1, __shfl_xor_sync(0xffffffffu, mx1, 2));
        mx2 = fmaxf(mx2, __shfl_xor_sync(0xffffffffu, mx2, 1));
        mx2 = fmaxf(mx2, __shfl_xor_sync(0xffffffffu, mx2, 2));
        float nm1 = fmaxf(m1, mx1), nm2 = fmaxf(m2, mx2);
        float f1 = __expf(m1 - nm1), f2v = __expf(m2 - nm2);
        m1 = nm1; m2 = nm2;
        float s1 = 0.f, s2 = 0.f;
        #pragma unroll
        for (int nt = 0; nt < 8; nt++) {
            sf[nt][0] = __expf(sf[nt][0] - nm1); s1 += sf[nt][0];
            sf[nt][1] = __expf(sf[nt][1] - nm1); s1 += sf[nt][1];
            sf[nt][2] = __expf(sf[nt][2] - nm2); s2 += sf[nt][2];
            sf[nt][3] = __expf(sf[nt][3] - nm2); s2 += sf[nt][3];
        }
        s1 += __shfl_xor_sync(0xffffffffu, s1, 1);
        s1 += __shfl_xor_sync(0xffffffffu, s1, 2);
        s2 += __shfl_xor_sync(0xffffffffu, s2, 1);
        s2 += __shfl_xor_sync(0xffffffffu, s2, 2);
        l1 = l1 * f1 + s1;
        l2 = l2 * f2v + s2;
        #pragma unroll
        for (int nt = 0; nt < 8; nt++) {
            of[nt][0] *= f1;  of[nt][1] *= f1;
            of[nt][2] *= f2v; of[nt][3] *= f2v;
        }

        #pragma unroll
        for (int g2 = 0; g2 < 4; g2++) {
            uint32_t pa0 = packh2(sf[2 * g2][0], sf[2 * g2][1]);
            uint32_t pa1 = packh2(sf[2 * g2][2], sf[2 * g2][3]);
            uint32_t pa2 = packh2(sf[2 * g2 + 1][0], sf[2 * g2 + 1][1]);
            uint32_t pa3 = packh2(sf[2 * g2 + 1][2], sf[2 * g2 + 1][3]);
            const int vrow = g2 * 16 + vrow_l;
            #pragma unroll
            for (int dp = 0; dp < 4; dp++) {
                uint32_t r0, r1, r2, r3;
                ldsm_x4t(r0, r1, r2, r3,
                         vA + SWZ((uint32_t)(vrow * 128) + (uint32_t)(dp * 32) + vcol_l));
                mma_f16(of[2 * dp],     pa0, pa1, pa2, pa3, r0, r1);
                mma_f16(of[2 * dp + 1], pa0, pa1, pa2, pa3, r2, r3);
            }
        }
        __syncthreads();
    }

    float inv1 = 1.0f / l1, inv2 = 1.0f / l2;
    __half* o1base = out + (size_t)(b * Ss_ + aq1) * Dd_ + h * HD_;
    __half* o2base = out + (size_t)(b * Ss_ + aq1 + 8) * Dd_ + h * HD_;
    #pragma unroll
    for (int nt = 0; nt < 8; nt++) {
        *(__half2*)(o1base + nt * 8 + qd * 2) = __floats2half2_rn(of[nt][0] * inv1, of[nt][1] * inv1);
        *(__half2*)(o2base + nt * 8 + qd * 2) = __floats2half2_rn(of[nt][2] * inv2, of[nt][3] * inv2);
    }
}

// -------------------- Cross-attention --------------------
__global__ __launch_bounds__(64)
void cross_attn_kernel(const __half* __restrict__ qch, const float* __restrict__ kvc,
                       __half* __restrict__ out)
{
    int qidx = blockIdx.x;
    int bh   = blockIdx.y;
    int b = bh / Hh_, h = bh % Hh_;
    int tid = threadIdx.x;

    __shared__ float sq[HD_];
    __shared__ float p[MEM_];
    __shared__ float red[2];

    const __half* qrow = qch + ((size_t)(b * Ss_ + qidx)) * Dd_ + h * HD_;
    sq[tid] = __half2float(qrow[tid]);
    __syncthreads();

    const float* krow = kvc + ((size_t)(b * MEM_ + tid)) * (2 * Dd_) + h * HD_;
    float s = 0.f;
    #pragma unroll
    for (int d = 0; d < HD_; d += 4) {
        float4 k4 = *(const float4*)(krow + d);
        s = fmaf(sq[d + 0], k4.x, s);
        s = fmaf(sq[d + 1], k4.y, s);
        s = fmaf(sq[d + 2], k4.z, s);
        s = fmaf(sq[d + 3], k4.w, s);
    }
    s *= 0.125f;

    float m = s;
    #pragma unroll
    for (int o = 16; o > 0; o >>= 1) m = fmaxf(m, __shfl_xor_sync(0xffffffffu, m, o));
    if ((tid & 31) == 0) red[tid >> 5] = m;
    __syncthreads();
    float gm = fmaxf(red[0], red[1]);
    float pv = expf(s - gm);
    p[tid] = pv;
    float su = pv;
    #pragma unroll
    for (int o = 16; o > 0; o >>= 1) su += __shfl_xor_sync(0xffffffffu, su, o);
    __syncthreads();
    if ((tid & 31) == 0) red[tid >> 5] = su;
    __syncthreads();
    float gl = red[0] + red[1];

    const float* vbase = kvc + ((size_t)(b * MEM_)) * (2 * Dd_) + Dd_ + h * HD_ + tid;
    float a = 0.f;
    #pragma unroll 4
    for (int j = 0; j < MEM_; j++)
        a = fmaf(p[j], vbase[(size_t)j * (2 * Dd_)], a);

    out[((size_t)(b * Ss_ + qidx)) * Dd_ + h * HD_ + tid] = __float2half_rn(a / gl);
}

// -------------------- launch --------------------
extern "C" void kernel_launch(void* const* d_in, const int* in_sizes, int n_in,
                              void* d_out, int out_size)
{
    const float* tgt      = (const float*)d_in[0];
    const float* memory   = (const float*)d_in[1];
    const float* rope_cos = (const float*)d_in[2];
    const float* rope_sin = (const float*)d_in[3];
    const float* W_qkv    = (const float*)d_in[4];
    const float* b_qkv    = (const float*)d_in[5];
    const float* W_o      = (const float*)d_in[6];
    const float* b_o      = (const float*)d_in[7];
    const float* Wq_c     = (const float*)d_in[8];
    const float* bq_c     = (const float*)d_in[9];
    const float* Wk_c     = (const float*)d_in[10];
    const float* bk_c     = (const float*)d_in[11];
    const float* Wv_c     = (const float*)d_in[12];
    const float* bv_c     = (const float*)d_in[13];
    const float* W_co     = (const float*)d_in[14];
    const float* b_co     = (const float*)d_in[15];
    const float* W1       = (const float*)d_in[16];
    const float* b1       = (const float*)d_in[17];
    const float* W2       = (const float*)d_in[18];
    const float* b2       = (const float*)d_in[19];
    const float* g1       = (const float*)d_in[20];
    const float* be1      = (const float*)d_in[21];
    const float* g2       = (const float*)d_in[22];
    const float* be2      = (const float*)d_in[23];
    const float* g3       = (const float*)d_in[24];
    const float* be3      = (const float*)d_in[25];
    float* out = (float*)d_out;

    float *tgtb, *kvc, *b2c;
    __half *wTh, *qkvh, *xh, *sah, *ffnh, *memh;
    cudaGetSymbolAddress((void**)&tgtb, g_tgt);
    cudaGetSymbolAddress((void**)&kvc,  g_kvc);
    cudaGetSymbolAddress((void**)&b2c,  g_b2);
    cudaGetSymbolAddress((void**)&wTh,  g_wTh);
    cudaGetSymbolAddress((void**)&qkvh, g_qkvh);
    cudaGetSymbolAddress((void**)&xh,   g_xh);
    cudaGetSymbolAddress((void**)&sah,  g_sah);
    cudaGetSymbolAddress((void**)&ffnh, g_ffnh);
    cudaGetSymbolAddress((void**)&memh, g_memh);

    cudaFuncSetAttribute(flash_attn_h,
                         cudaFuncAttributeMaxDynamicSharedMemorySize, FAH_SMEM);
    cudaFuncSetAttribute(gemm_mma,
                         cudaFuncAttributeMaxDynamicSharedMemorySize, GA_SMEM);
    cudaFuncSetAttribute(gemm_qkv,
                         cudaFuncAttributeMaxDynamicSharedMemorySize, GA_SMEM);

    // 0) fused preprocessing
    prep_all<<<16904, dim3(32, 8)>>>(W_qkv, W_o, Wq_c, Wk_c, Wv_c, W_co, W1, W2,
                                     memory, bk_c, bv_c);

    // 1) xh = LN1(tgt)
    layernorm_kernel<<<NT_, 256>>>(tgt, g1, be1, xh);
    // 2) qkvh = RoPE(xh @ W_qkv + b)
    gemm_qkv<<<dim3(3 * Dd_ / 128, NT_ / 128), 128, GA_SMEM>>>(
        xh, wTh + WT_QKV, b_qkv, qkvh, rope_cos, rope_sin, 3 * Dd_, Dd_);
    // 3) causal self-attention -> sah
    flash_attn_h<<<dim3(Ss_ / 64, Bb_ * Hh_), 128, FAH_SMEM>>>(qkvh, sah);
    // 4) tgtb = tgt + sah @ W_o + b_o
    gemm_mma<<<dim3(Dd_ / 128, NT_ / 128), 128, GA_SMEM>>>(
        sah, wTh + WT_O, b_o, tgt, tgtb, nullptr, Dd_, Dd_, 0);
    // 5) xh = LN2(tgtb)
    layernorm_kernel<<<NT_, 256>>>(tgtb, g2, be2, xh);
    // 6) qch = xh @ Wq_c (fp16 out)
    gemm_mma<<<dim3(Dd_ / 128, NT_ / 128), 128, GA_SMEM>>>(
        xh, wTh + WT_QC, bq_c, nullptr, nullptr, qkvh, Dd_, Dd_, 0);
    // 7) kvc = memh @ [Wk_c|Wv_c]
    gemm_mma<<<dim3(2 * Dd_ / 128, 1), 128, GA_SMEM>>>(
        memh, wTh + WT_KC, b2c, nullptr, kvc, nullptr, 2 * Dd_, Dd_, 0);
    // 8) cross-attention -> sah
    cross_attn_kernel<<<dim3(Ss_, Bb_ * Hh_), 64>>>(qkvh, kvc, sah);
    // 9) tgtb += sah @ W_co + b_co
    gemm_mma<<<dim3(Dd_ / 128, NT_ / 128), 128, GA_SMEM>>>(
        sah, wTh + WT_CO, b_co, tgtb, tgtb, nullptr, Dd_, Dd_, 0);
    // 10) xh = LN3(tgtb)
    layernorm_kernel<<<NT_, 256>>>(tgtb, g3, be3, xh);
    // 11) ffnh = gelu(xh @ W1 + b1)
    gemm_mma<<<dim3(FF_ / 128, NT_ / 128), 128, GA_SMEM>>>(
        xh, wTh + WT_W1, b1, nullptr, nullptr, ffnh, FF_, Dd_, 1);
    // 12) out = tgtb + ffnh @ W2 + b2
    gemm_mma<<<dim3(Dd_ / 128, NT_ / 128), 128, GA_SMEM>>>(
        ffnh, wTh + WT_W2, b2, tgtb, out, nullptr, Dd_, FF_, 0);
}

// round 16
// speedup vs baseline: 1.1699x; 1.0214x over previous
#include <cuda_runtime.h>
#include <cuda_fp16.h>
#include <cstdint>
#include <math.h>

// Problem constants
#define Bb_  2
#define Ss_  2048
#define MEM_ 64
#define Dd_  1024
#define Hh_  16
#define FF_  4096
#define HD_  64
#define NT_  (Bb_ * Ss_)   // 4096 tokens

// -------------------- scratch (device globals; no runtime alloc) --------------------
__device__ float  g_tgt [(size_t)NT_ * Dd_];
__device__ float  g_kvc [(size_t)Bb_ * MEM_ * 2 * Dd_];
__device__ float  g_b2  [2 * Dd_];
__device__ __half g_wTh [(size_t)16 * 1024 * 1024];
__device__ __half g_qkvh[(size_t)NT_ * 3 * Dd_];     // qkv (pre-roped/scaled) / qc
__device__ __half g_xh  [(size_t)NT_ * Dd_];
__device__ __half g_sah [(size_t)NT_ * Dd_];
__device__ __half g_ffnh[(size_t)NT_ * FF_];
__device__ __half g_memh[(size_t)Bb_ * MEM_ * Dd_];

#define WT_QKV 0u
#define WT_O   (3u * 1024u * 1024u)
#define WT_QC  (4u * 1024u * 1024u)
#define WT_KC  (5u * 1024u * 1024u)
#define WT_VC  (6u * 1024u * 1024u)
#define WT_CO  (7u * 1024u * 1024u)
#define WT_W1  (8u * 1024u * 1024u)
#define WT_W2  (12u * 1024u * 1024u)

// -------------------- helpers --------------------
__device__ __forceinline__ uint32_t smem_u32(const void* p) {
    uint32_t a;
    asm("{ .reg .u64 t; cvta.to.shared.u64 t, %1; cvt.u32.u64 %0, t; }" : "=r"(a) : "l"(p));
    return a;
}
__device__ __forceinline__ void cpa16(uint32_t dst, const void* src) {
    asm volatile("cp.async.cg.shared.global [%0], [%1], 16;" :: "r"(dst), "l"(src));
}
__device__ __forceinline__ void ldsm_x4(uint32_t& r0, uint32_t& r1, uint32_t& r2,
                                        uint32_t& r3, uint32_t addr) {
    asm volatile("ldmatrix.sync.aligned.m8n8.x4.shared.b16 {%0,%1,%2,%3}, [%4];"
                 : "=r"(r0), "=r"(r1), "=r"(r2), "=r"(r3) : "r"(addr));
}
__device__ __forceinline__ void ldsm_x4t(uint32_t& r0, uint32_t& r1, uint32_t& r2,
                                         uint32_t& r3, uint32_t addr) {
    asm volatile("ldmatrix.sync.aligned.m8n8.x4.trans.shared.b16 {%0,%1,%2,%3}, [%4];"
                 : "=r"(r0), "=r"(r1), "=r"(r2), "=r"(r3) : "r"(addr));
}
#define CPA_COMMIT() asm volatile("cp.async.commit_group;" ::: "memory")
#define CPA_WAIT1()  asm volatile("cp.async.wait_group 1;"  ::: "memory")
#define CPA_WAIT0()  asm volatile("cp.async.wait_group 0;"  ::: "memory")
#define SWZ(b) ((b) ^ (((b) >> 3) & 0x70))

__device__ __forceinline__ void mma_f16(float* d, uint32_t a0, uint32_t a1, uint32_t a2,
                                        uint32_t a3, uint32_t b0, uint32_t b1) {
    asm volatile(
        "mma.sync.aligned.m16n8k16.row.col.f32.f16.f16.f32 "
        "{%0,%1,%2,%3}, {%4,%5,%6,%7}, {%8,%9}, {%0,%1,%2,%3};"
        : "+f"(d[0]), "+f"(d[1]), "+f"(d[2]), "+f"(d[3])
        : "r"(a0), "r"(a1), "r"(a2), "r"(a3), "r"(b0), "r"(b1));
}
__device__ __forceinline__ uint32_t packh2(float a, float b) {
    __half2 h = __floats2half2_rn(a, b);
    return *reinterpret_cast<uint32_t*>(&h);
}
__device__ __forceinline__ float gelu1(float x) {
    return 0.5f * x * (1.0f + erff(x * 0.7071067811865475f));
}

// -------------------- fused preprocessing --------------------
__global__ void prep_all(const float* __restrict__ W_qkv, const float* __restrict__ W_o,
                         const float* __restrict__ Wq_c, const float* __restrict__ Wk_c,
                         const float* __restrict__ Wv_c, const float* __restrict__ W_co,
                         const float* __restrict__ W1,   const float* __restrict__ W2,
                         const float* __restrict__ memory,
                         const float* __restrict__ bk_c, const float* __restrict__ bv_c)
{
    __shared__ float t[32][33];
    __half* wTh = g_wTh;
    const int bid = blockIdx.x;
    const int tx = threadIdx.x, ty = threadIdx.y;
    const int tid = ty * 32 + tx;

    if (bid < 16384) {
        const float* W; __half* WT; int K, N, lb;
        if (bid < 3072)       { W = W_qkv; WT = wTh + WT_QKV; K = Dd_; N = 3 * Dd_; lb = bid; }
        else if (bid < 4096)  { W = W_o;   WT = wTh + WT_O;   K = Dd_; N = Dd_;     lb = bid - 3072; }
        else if (bid < 5120)  { W = Wq_c;  WT = wTh + WT_QC;  K = Dd_; N = Dd_;     lb = bid - 4096; }
        else if (bid < 6144)  { W = Wk_c;  WT = wTh + WT_KC;  K = Dd_; N = Dd_;     lb = bid - 5120; }
        else if (bid < 7168)  { W = Wv_c;  WT = wTh + WT_VC;  K = Dd_; N = Dd_;     lb = bid - 6144; }
        else if (bid < 8192)  { W = W_co;  WT = wTh + WT_CO;  K = Dd_; N = Dd_;     lb = bid - 7168; }
        else if (bid < 12288) { W = W1;    WT = wTh + WT_W1;  K = Dd_; N = FF_;     lb = bid - 8192; }
        else                  { W = W2;    WT = wTh + WT_W2;  K = FF_; N = Dd_;     lb = bid - 12288; }
        const int nbx = N / 32;
        const int n0 = (lb % nbx) * 32, k0 = (lb / nbx) * 32;
        #pragma unroll
        for (int r = 0; r < 32; r += 8)
            t[ty + r][tx] = W[(size_t)(k0 + ty + r) * N + n0 + tx];
        __syncthreads();
        #pragma unroll
        for (int r = 0; r < 32; r += 8)
            WT[(size_t)(n0 + ty + r) * K + k0 + tx] = __float2half_rn(t[tx][ty + r]);
    } else if (bid < 16896) {
        int i = (bid - 16384) * 256 + tid;
        g_memh[i] = __float2half_rn(memory[i]);
    } else {
        int i = (bid - 16896) * 256 + tid;
        if (i < Dd_) g_b2[i] = bk_c[i];
        else         g_b2[i] = bv_c[i - Dd_];
    }
}

// -------------------- LayerNorm (fp32 in, fp16 out) --------------------
__global__ void layernorm_kernel(const float* __restrict__ x,
                                 const float* __restrict__ g,
                                 const float* __restrict__ be,
                                 __half* __restrict__ y)
{
    int row = blockIdx.x;
    int tid = threadIdx.x;
    const float* xr = x + (size_t)row * Dd_;
    float4 v = *(const float4*)(xr + tid * 4);

    __shared__ float red[8];
    __shared__ float s_mu, s_inv;

    float s = v.x + v.y + v.z + v.w;
    #pragma unroll
    for (int o = 16; o > 0; o >>= 1) s += __shfl_xor_sync(0xffffffffu, s, o);
    if ((tid & 31) == 0) red[tid >> 5] = s;
    __syncthreads();
    if (tid == 0) {
        float t = 0.f;
        #pragma unroll
        for (int i = 0; i < 8; i++) t += red[i];
        s_mu = t * (1.0f / Dd_);
    }
    __syncthreads();
    float mu = s_mu;
    float dx = v.x - mu, dy = v.y - mu, dz = v.z - mu, dw = v.w - mu;
    float q = dx*dx + dy*dy + dz*dz + dw*dw;
    #pragma unroll
    for (int o = 16; o > 0; o >>= 1) q += __shfl_xor_sync(0xffffffffu, q, o);
    if ((tid & 31) == 0) red[tid >> 5] = q;
    __syncthreads();
    if (tid == 0) {
        float t = 0.f;
        #pragma unroll
        for (int i = 0; i < 8; i++) t += red[i];
        s_inv = rsqrtf(t * (1.0f / Dd_) + 1e-5f);
    }
    __syncthreads();
    float inv = s_inv;
    int c = tid * 4;
    __half* yr = y + (size_t)row * Dd_;
    float o0 = dx * inv * g[c + 0] + be[c + 0];
    float o1 = dy * inv * g[c + 1] + be[c + 1];
    float o2 = dz * inv * g[c + 2] + be[c + 2];
    float o3 = dw * inv * g[c + 3] + be[c + 3];
    ((__half2*)(yr + c))[0] = __floats2half2_rn(o0, o1);
    ((__half2*)(yr + c))[1] = __floats2half2_rn(o2, o3);
}

// ======== GEMM mainloop macro: CTA 128x128, 128 threads, 4 warps 64x64, 3-stage =====
// Expects ints bx, by (tile coords) already defined; defines everything else.
#define GA_STAGE 32768
#define GA_SMEM  (3 * GA_STAGE + 1024)
#define GEMM_PROLOG_AND_MAINLOOP()                                                     \
    extern __shared__ float dyns[];                                                   \
    const uint32_t sbase = (smem_u32(dyns) + 1023u) & ~1023u;                          \
    const int tid  = threadIdx.x;                                                     \
    const int lane = tid & 31, wid = tid >> 5;                                        \
    const int gid  = lane >> 2, qd = lane & 3;                                        \
    const int wm   = (wid >> 1) * 64;                                                 \
    const int wn   = (wid & 1) * 64;                                                  \
    const int n0   = bx * 128;                                                        \
    const int m0   = by * 128;                                                        \
    const int arow  = wm + (lane & 7) + ((lane >> 3) & 1) * 8;                        \
    const uint32_t acolb = (uint32_t)((lane >> 4) * 16);                              \
    const int bn_base = wn + ((lane >> 4) & 1) * 8 + (lane & 7);                      \
    const uint32_t bcolb = (uint32_t)(((lane >> 3) & 1) * 16);                        \
    float d[4][8][4];                                                                 \
    _Pragma("unroll")                                                                 \
    for (int mt = 0; mt < 4; mt++)                                                    \
        _Pragma("unroll")                                                             \
        for (int nt = 0; nt < 8; nt++)                                                \
            _Pragma("unroll")                                                         \
            for (int e = 0; e < 4; e++) d[mt][nt][e] = 0.f;                           \
    const int nsteps = Kd >> 6;                                                       \
    const __half* Abase = A  + (size_t)m0 * Kd;                                       \
    const __half* Bbase = WT + (size_t)n0 * Kd;                                       \
    auto cpa_tile = [&](int kstep, int s) {                                           \
        const int k0 = kstep * 64;                                                    \
        const uint32_t aA = sbase + s * GA_STAGE;                                     \
        const uint32_t bA = aA + 16384u;                                              \
        _Pragma("unroll")                                                             \
        for (int p = 0; p < 8; p++) {                                                 \
            int task = p * 128 + tid;                                                 \
            int r = task >> 3, c = task & 7;                                          \
            cpa16(aA + SWZ((uint32_t)(r * 128 + c * 16)),                             \
                  Abase + (size_t)r * Kd + k0 + c * 8);                               \
        }                                                                             \
        _Pragma("unroll")                                                             \
        for (int p = 0; p < 8; p++) {                                                 \
            int task = p * 128 + tid;                                                 \
            int r = task >> 3, c = task & 7;                                          \
            cpa16(bA + SWZ((uint32_t)(r * 128 + c * 16)),                             \
                  Bbase + (size_t)r * Kd + k0 + c * 8);                               \
        }                                                                             \
        CPA_COMMIT();                                                                 \
    };                                                                                \
    cpa_tile(0, 0);                                                                   \
    cpa_tile(1, 1);                                                                   \
    for (int i = 0; i < nsteps; i++) {                                                \
        const int s = i % 3;                                                          \
        if (i == nsteps - 1) { CPA_WAIT0(); } else { CPA_WAIT1(); }                   \
        __syncthreads();                                                              \
        if (i + 2 < nsteps) cpa_tile(i + 2, (i + 2) % 3);                             \
        const uint32_t aA = sbase + s * GA_STAGE;                                     \
        const uint32_t bA = aA + 16384u;                                              \
        _Pragma("unroll")                                                             \
        for (int g = 0; g < 4; g++) {                                                 \
            const uint32_t gb = (uint32_t)(g * 32);                                   \
            uint32_t am[4][4];                                                        \
            _Pragma("unroll")                                                         \
            for (int mt = 0; mt < 4; mt++)                                            \
                ldsm_x4(am[mt][0], am[mt][1], am[mt][2], am[mt][3],                   \
                        aA + SWZ((uint32_t)((arow + mt * 16) * 128) + gb + acolb));   \
            uint32_t bf[8][2];                                                        \
            _Pragma("unroll")                                                         \
            for (int jp = 0; jp < 4; jp++) {                                          \
                int n = bn_base + jp * 16;                                            \
                ldsm_x4(bf[jp * 2][0], bf[jp * 2][1],                                 \
                        bf[jp * 2 + 1][0], bf[jp * 2 + 1][1],                         \
                        bA + SWZ((uint32_t)(n * 128) + gb + bcolb));                  \
            }                                                                         \
            _Pragma("unroll")                                                         \
            for (int mt = 0; mt < 4; mt++)                                            \
                _Pragma("unroll")                                                     \
                for (int nt = 0; nt < 8; nt++)                                        \
                    mma_f16(d[mt][nt], am[mt][0], am[mt][1], am[mt][2], am[mt][3],    \
                            bf[nt][0], bf[nt][1]);                                    \
        }                                                                             \
    }

// ============ GEMM (general) ==============================
__global__ __launch_bounds__(128)
void gemm_mma(const __half* __restrict__ A, const __half* __restrict__ WT,
              const float* __restrict__ bias, const float* __restrict__ res,
              float* __restrict__ C, __half* __restrict__ Ch,
              int Nc, int Kd, int dogelu)
{
    const int bx = blockIdx.x, by = blockIdx.y;
    GEMM_PROLOG_AND_MAINLOOP();

    #pragma unroll
    for (int mt = 0; mt < 4; mt++) {
        #pragma unroll
        for (int nt = 0; nt < 8; nt++) {
            const int r0  = m0 + wm + mt * 16 + gid;
            const int col = n0 + wn + nt * 8 + qd * 2;
            float2 b2 = *(const float2*)(bias + col);
            #pragma unroll
            for (int half_ = 0; half_ < 2; half_++) {
                const int row = r0 + half_ * 8;
                float ox = d[mt][nt][half_ * 2 + 0] + b2.x;
                float oy = d[mt][nt][half_ * 2 + 1] + b2.y;
                if (res) {
                    float2 r2 = *(const float2*)(res + (size_t)row * Nc + col);
                    ox += r2.x; oy += r2.y;
                }
                if (dogelu) { ox = gelu1(ox); oy = gelu1(oy); }
                if (Ch) {
                    *(__half2*)(Ch + (size_t)row * Nc + col) = __floats2half2_rn(ox, oy);
                } else {
                    float2 o2; o2.x = ox; o2.y = oy;
                    *(float2*)(C + (size_t)row * Nc + col) = o2;
                }
            }
        }
    }
}

// ============ GEMM (QKV only): RoPE + Q-scale fused epilogue, fp16 out ==============
__global__ __launch_bounds__(128)
void gemm_qkv(const __half* __restrict__ A, const __half* __restrict__ WT,
              const float* __restrict__ bias, __half* __restrict__ Ch,
              const float* __restrict__ rc, const float* __restrict__ rs,
              int Nc, int Kd)
{
    const int bx = blockIdx.x, by = blockIdx.y;
    GEMM_PROLOG_AND_MAINLOOP();

    #pragma unroll
    for (int mt = 0; mt < 4; mt++) {
        #pragma unroll
        for (int nt = 0; nt < 8; nt++) {
            const int r0  = m0 + wm + mt * 16 + gid;
            const int col = n0 + wn + nt * 8 + qd * 2;
            float2 b2 = *(const float2*)(bias + col);
            #pragma unroll
            for (int half_ = 0; half_ < 2; half_++) {
                const int row = r0 + half_ * 8;
                float ox = d[mt][nt][half_ * 2 + 0] + b2.x;
                float oy = d[mt][nt][half_ * 2 + 1] + b2.y;
                if (col < 2 * Dd_) {
                    int pos  = row & (Ss_ - 1);
                    int pidx = (col & 63) >> 1;
                    float c  = rc[pos * 32 + pidx];
                    float sn = rs[pos * 32 + pidx];
                    float re = ox * c - oy * sn;
                    float im = ox * sn + oy * c;
                    if (col < Dd_) { re *= 0.125f; im *= 0.125f; }
                    ox = re; oy = im;
                }
                *(__half2*)(Ch + (size_t)row * Nc + col) = __floats2half2_rn(ox, oy);
            }
        }
    }
}

// ============ GEMM (qc + kvc merged, flattened 272-CTA grid) ========================
// bid < 256: qc = xh @ Wq_c + bq -> qkvh (fp16), Nc=1024, bx=bid%8, by=bid/8
// bid >= 256: kvc = memh @ [Wk|Wv] + b2 -> kvc (fp32), Nc=2048, bx=bid-256, by=0
__global__ __launch_bounds__(128)
void gemm_qckv(const __half* __restrict__ Aq, const __half* __restrict__ WTq,
               const float* __restrict__ biasq, __half* __restrict__ Chq,
               const __half* __restrict__ Am, const __half* __restrict__ WTm,
               const float* __restrict__ biasm, float* __restrict__ Cm,
               int Kd)
{
    const int bid = blockIdx.x;
    const bool isq = (bid < 256);
    const int bx = isq ? (bid & 7) : (bid - 256);
    const int by = isq ? (bid >> 3) : 0;
    const __half* A  = isq ? Aq  : Am;
    const __half* WT = isq ? WTq : WTm;
    const float* bias = isq ? biasq : biasm;
    const int Nc = isq ? Dd_ : 2 * Dd_;

    GEMM_PROLOG_AND_MAINLOOP();

    #pragma unroll
    for (int mt = 0; mt < 4; mt++) {
        #pragma unroll
        for (int nt = 0; nt < 8; nt++) {
            const int r0  = m0 + wm + mt * 16 + gid;
            const int col = n0 + wn + nt * 8 + qd * 2;
            float2 b2 = *(const float2*)(bias + col);
            #pragma unroll
            for (int half_ = 0; half_ < 2; half_++) {
                const int row = r0 + half_ * 8;
                float ox = d[mt][nt][half_ * 2 + 0] + b2.x;
                float oy = d[mt][nt][half_ * 2 + 1] + b2.y;
                if (isq) {
                    *(__half2*)(Chq + (size_t)row * Nc + col) = __floats2half2_rn(ox, oy);
                } else {
                    float2 o2; o2.x = ox; o2.y = oy;
                    *(float2*)(Cm + (size_t)row * Nc + col) = o2;
                }
            }
        }
    }
}

// -------------------- fp16 mma flash attention, paired q-tiles, cp.async DB ----------
// grid.x = 16: block bx processes q-tiles {bx, 31-bx} -> uniform 33 KV-tiles/block.
#define FAH_SMEM 32768
#define NQT (Ss_ / 64)
__global__ __launch_bounds__(128)
void flash_attn_h(const __half* __restrict__ qkvh, __half* __restrict__ out)
{
    extern __shared__ __half smh[];
    const uint32_t sb = smem_u32(smh);
    const uint32_t kAs[2] = { sb,          sb + 16384u };
    const uint32_t vAs[2] = { sb + 8192u,  sb + 24576u };

    const int bh = blockIdx.y;
    const int b = bh >> 4, h = bh & 15;
    const int tid = threadIdx.x, lane = tid & 31, wid = tid >> 5;
    const int gid = lane >> 2, qd = lane & 3;
    const int wr = wid * 16;
    const int rs3 = 3 * Dd_;

    const __half* kbase = qkvh + (size_t)(b * Ss_) * rs3 + Dd_ + h * HD_;
    const __half* vbase = qkvh + (size_t)(b * Ss_) * rs3 + 2 * Dd_ + h * HD_;

    const int bn_base = ((lane >> 4) & 1) * 8 + (lane & 7);
    const uint32_t bcolb = (uint32_t)(((lane >> 3) & 1) * 16);
    const int vrow_l = (lane & 7) + ((lane >> 3) & 1) * 8;
    const uint32_t vcol_l = (uint32_t)(((lane >> 4) & 1) * 16);

    #pragma unroll 1
    for (int halfb = 0; halfb < 2; halfb++) {
        const int qb = halfb ? (NQT - 1 - (int)blockIdx.x) : (int)blockIdx.x;
        const int q0 = qb * 64;
        const __half* qbase = qkvh + (size_t)(b * Ss_ + q0) * rs3 + h * HD_;

        // stage Q into kAs[0], load A-frags
        {
            #pragma unroll
            for (int p = 0; p < 4; p++) {
                int task = p * 128 + tid;
                int r = task >> 3, c = task & 7;
                cpa16(kAs[0] + SWZ((uint32_t)(r * 128 + c * 16)), qbase + (size_t)r * rs3 + c * 8);
            }
            CPA_COMMIT();
            CPA_WAIT0();
            __syncthreads();
        }
        uint32_t qf[4][4];
        {
            const int ar = wr + (lane & 7) + ((lane >> 3) & 1) * 8;
            const uint32_t ac = (uint32_t)((lane >> 4) * 16);
            #pragma unroll
            for (int g = 0; g < 4; g++)
                ldsm_x4(qf[g][0], qf[g][1], qf[g][2], qf[g][3],
                        kAs[0] + SWZ((uint32_t)(ar * 128) + (uint32_t)(g * 32) + ac));
        }
        __syncthreads();

        auto cpa_kv = [&](int t, int s) {
            const int k0 = t * 64;
            #pragma unroll
            for (int p = 0; p < 4; p++) {
                int task = p * 128 + tid;
                int r = task >> 3, c = task & 7;
                cpa16(kAs[s] + SWZ((uint32_t)(r * 128 + c * 16)),
                      kbase + (size_t)(k0 + r) * rs3 + c * 8);
            }
            #pragma unroll
            for (int p = 0; p < 4; p++) {
                int task = p * 128 + tid;
                int r = task >> 3, c = task & 7;
                cpa16(vAs[s] + SWZ((uint32_t)(r * 128 + c * 16)),
                      vbase + (size_t)(k0 + r) * rs3 + c * 8);
            }
            CPA_COMMIT();
        };

        float of[8][4];
        #pragma unroll
        for (int nt = 0; nt < 8; nt++)
            #pragma unroll
            for (int e = 0; e < 4; e++) of[nt][e] = 0.f;
        float m1 = -1e30f, m2 = -1e30f, l1 = 0.f, l2 = 0.f;
        const int aq1 = q0 + wr + gid;

        cpa_kv(0, 0);

        for (int t = 0; t <= qb; t++) {
            const int s = t & 1;
            if (t < qb) { cpa_kv(t + 1, s ^ 1); CPA_WAIT1(); }
            else        { CPA_WAIT0(); }
            __syncthreads();

            const uint32_t kA = kAs[s], vA = vAs[s];
            const int k0 = t * 64;

            float sf[8][4];
            #pragma unroll
            for (int nt = 0; nt < 8; nt++)
                #pragma unroll
                for (int e = 0; e < 4; e++) sf[nt][e] = 0.f;

            #pragma unroll
            for (int g = 0; g < 4; g++) {
                const uint32_t gb = (uint32_t)(g * 32);
                uint32_t kb[8][2];
                #pragma unroll
                for (int jp = 0; jp < 4; jp++) {
                    int n = bn_base + jp * 16;
                    ldsm_x4(kb[jp * 2][0], kb[jp * 2][1], kb[jp * 2 + 1][0], kb[jp * 2 + 1][1],
                            kA + SWZ((uint32_t)(n * 128) + gb + bcolb));
                }
                #pragma unroll
                for (int nt = 0; nt < 8; nt++)
                    mma_f16(sf[nt], qf[g][0], qf[g][1], qf[g][2], qf[g][3], kb[nt][0], kb[nt][1]);
            }

            if (t == qb) {
                #pragma unroll
                for (int nt = 0; nt < 8; nt++) {
                    int c = k0 + nt * 8 + qd * 2;
                    if (c     > aq1)     sf[nt][0] = -1e30f;
                    if (c + 1 > aq1)     sf[nt][1] = -1e30f;
                    if (c     > aq1 + 8) sf[nt][2] = -1e30f;
                    if (c + 1 > aq1 + 8) sf[nt][3] = -1e30f;
                }
            }

            float mx1 = -1e30f, mx2 = -1e30f;
            #pragma unroll
            for (int nt = 0; nt < 8; nt++) {
                mx1 = fmaxf(mx1, fmaxf(sf[nt][0], sf[nt][1]));
                mx2 = fmaxf(mx2, fmaxf(sf[nt][2], sf[nt][3]));
            }
            mx1 = fmaxf(mx1, __shfl_xor_sync(0xffffffffu, mx1, 1));
            mx1 = fmaxf(mx1, __shfl_xor_sync(0xffffffffu, mx1, 2));
            mx2 = fmaxf(mx2, __shfl_xor_sync(0xffffffffu, mx2, 1));
            mx2 = fmaxf(mx2, __shfl_xor_sync(0xffffffffu, mx2, 2));
            float nm1 = fmaxf(m1, mx1), nm2 = fmaxf(m2, mx2);
            float f1 = __expf(m1 - nm1), f2v = __expf(m2 - nm2);
            m1 = nm1; m2 = nm2;
            float s1 = 0.f, s2 = 0.f;
            #pragma unroll
            for (int nt = 0; nt < 8; nt++) {
                sf[nt][0] = __expf(sf[nt][0] - nm1); s1 += sf[nt][0];
                sf[nt][1] = __expf(sf[nt][1] - nm1); s1 += sf[nt][1];
                sf[nt][2] = __expf(sf[nt][2] - nm2); s2 += sf[nt][2];
                sf[nt][3] = __expf(sf[nt][3] - nm2); s2 += sf[nt][3];
            }
            s1 += __shfl_xor_sync(0xffffffffu, s1, 1);
            s1 += __shfl_xor_sync(0xffffffffu, s1, 2);
            s2 += __shfl_xor_sync(0xffffffffu, s2, 1);
            s2 += __shfl_xor_sync(0xffffffffu, s2, 2);
            l1 = l1 * f1 + s1;
            l2 = l2 * f2v + s2;
            #pragma unroll
            for (int nt = 0; nt < 8; nt++) {
                of[nt][0] *= f1;  of[nt][1] *= f1;
                of[nt][2] *= f2v; of[nt][3] *= f2v;
            }

            #pragma unroll
            for (int g2 = 0; g2 < 4; g2++) {
                uint32_t pa0 = packh2(sf[2 * g2][0], sf[2 * g2][1]);
                uint32_t pa1 = packh2(sf[2 * g2][2], sf[2 * g2][3]);
                uint32_t pa2 = packh2(sf[2 * g2 + 1][0], sf[2 * g2 + 1][1]);
                uint32_t pa3 = packh2(sf[2 * g2 + 1][2], sf[2 * g2 + 1][3]);
                const int vrow = g2 * 16 + vrow_l;
                #pragma unroll
                for (int dp = 0; dp < 4; dp++) {
                    uint32_t r0, r1, r2, r3;
                    ldsm_x4t(r0, r1, r2, r3,
                             vA + SWZ((uint32_t)(vrow * 128) + (uint32_t)(dp * 32) + vcol_l));
                    mma_f16(of[2 * dp],     pa0, pa1, pa2, pa3, r0, r1);
                    mma_f16(of[2 * dp + 1], pa0, pa1, pa2, pa3, r2, r3);
                }
            }
            __syncthreads();
        }

        float inv1 = 1.0f / l1, inv2 = 1.0f / l2;
        __half* o1base = out + (size_t)(b * Ss_ + aq1) * Dd_ + h * HD_;
        __half* o2base = out + (size_t)(b * Ss_ + aq1 + 8) * Dd_ + h * HD_;
        #pragma unroll
        for (int nt = 0; nt < 8; nt++) {
            *(__half2*)(o1base + nt * 8 + qd * 2) = __floats2half2_rn(of[nt][0] * inv1, of[nt][1] * inv1);
            *(__half2*)(o2base + nt * 8 + qd * 2) = __floats2half2_rn(of[nt][2] * inv2, of[nt][3] * inv2);
        }
    }
}

// -------------------- Cross-attention --------------------
__global__ __launch_bounds__(64)
void cross_attn_kernel(const __half* __restrict__ qch, const float* __restrict__ kvc,
                       __half* __restrict__ out)
{
    int qidx = blockIdx.x;
    int bh   = blockIdx.y;
    int b = bh / Hh_, h = bh % Hh_;
    int tid = threadIdx.x;

    __shared__ float sq[HD_];
    __shared__ float p[MEM_];
    __shared__ float red[2];

    const __half* qrow = qch + ((size_t)(b * Ss_ + qidx)) * Dd_ + h * HD_;
    sq[tid] = __half2float(qrow[tid]);
    __syncthreads();

    const float* krow = kvc + ((size_t)(b * MEM_ + tid)) * (2 * Dd_) + h * HD_;
    float s = 0.f;
    #pragma unroll
    for (int d = 0; d < HD_; d += 4) {
        float4 k4 = *(const float4*)(krow + d);
        s = fmaf(sq[d + 0], k4.x, s);
        s = fmaf(sq[d + 1], k4.y, s);
        s = fmaf(sq[d + 2], k4.z, s);
        s = fmaf(sq[d + 3], k4.w, s);
    }
    s *= 0.125f;

    float m = s;
    #pragma unroll
    for (int o = 16; o > 0; o >>= 1) m = fmaxf(m, __shfl_xor_sync(0xffffffffu, m, o));
    if ((tid & 31) == 0) red[tid >> 5] = m;
    __syncthreads();
    float gm = fmaxf(red[0], red[1]);
    float pv = expf(s - gm);
    p[tid] = pv;
    float su = pv;
    #pragma unroll
    for (int o = 16; o > 0; o >>= 1) su += __shfl_xor_sync(0xffffffffu, su, o);
    __syncthreads();
    if ((tid & 31) == 0) red[tid >> 5] = su;
    __syncthreads();
    float gl = red[0] + red[1];

    const float* vbase = kvc + ((size_t)(b * MEM_)) * (2 * Dd_) + Dd_ + h * HD_ + tid;
    float a = 0.f;
    #pragma unroll 4
    for (int j = 0; j < MEM_; j++)
        a = fmaf(p[j], vbase[(size_t)j * (2 * Dd_)], a);

    out[((size_t)(b * Ss_ + qidx)) * Dd_ + h * HD_ + tid] = __float2half_rn(a / gl);
}

// -------------------- launch --------------------
extern "C" void kernel_launch(void* const* d_in, const int* in_sizes, int n_in,
                              void* d_out, int out_size)
{
    const float* tgt      = (const float*)d_in[0];
    const float* memory   = (const float*)d_in[1];
    const float* rope_cos = (const float*)d_in[2];
    const float* rope_sin = (const float*)d_in[3];
    const float* W_qkv    = (const float*)d_in[4];
    const float* b_qkv    = (const float*)d_in[5];
    const float* W_o      = (const float*)d_in[6];
    const float* b_o      = (const float*)d_in[7];
    const float* Wq_c     = (const float*)d_in[8];
    const float* bq_c     = (const float*)d_in[9];
    const float* Wk_c     = (const float*)d_in[10];
    const float* bk_c     = (const float*)d_in[11];
    const float* Wv_c     = (const float*)d_in[12];
    const float* bv_c     = (const float*)d_in[13];
    const float* W_co     = (const float*)d_in[14];
    const float* b_co     = (const float*)d_in[15];
    const float* W1       = (const float*)d_in[16];
    const float* b1       = (const float*)d_in[17];
    const float* W2       = (const float*)d_in[18];
    const float* b2       = (const float*)d_in[19];
    const float* g1       = (const float*)d_in[20];
    const float* be1      = (const float*)d_in[21];
    const float* g2       = (const float*)d_in[22];
    const float* be2      = (const float*)d_in[23];
    const float* g3       = (const float*)d_in[24];
    const float* be3      = (const float*)d_in[25];
    float* out = (float*)d_out;

    float *tgtb, *kvc, *b2c;
    __half *wTh, *qkvh, *xh, *sah, *ffnh, *memh;
    cudaGetSymbolAddress((void**)&tgtb, g_tgt);
    cudaGetSymbolAddress((void**)&kvc,  g_kvc);
    cudaGetSymbolAddress((void**)&b2c,  g_b2);
    cudaGetSymbolAddress((void**)&wTh,  g_wTh);
    cudaGetSymbolAddress((void**)&qkvh, g_qkvh);
    cudaGetSymbolAddress((void**)&xh,   g_xh);
    cudaGetSymbolAddress((void**)&sah,  g_sah);
    cudaGetSymbolAddress((void**)&ffnh, g_ffnh);
    cudaGetSymbolAddress((void**)&memh, g_memh);

    cudaFuncSetAttribute(flash_attn_h,
                         cudaFuncAttributeMaxDynamicSharedMemorySize, FAH_SMEM);
    cudaFuncSetAttribute(gemm_mma,
                         cudaFuncAttributeMaxDynamicSharedMemorySize, GA_SMEM);
    cudaFuncSetAttribute(gemm_qkv,
                         cudaFuncAttributeMaxDynamicSharedMemorySize, GA_SMEM);
    cudaFuncSetAttribute(gemm_qckv,
                         cudaFuncAttributeMaxDynamicSharedMemorySize, GA_SMEM);

    // 0) fused preprocessing
    prep_all<<<16904, dim3(32, 8)>>>(W_qkv, W_o, Wq_c, Wk_c, Wv_c, W_co, W1, W2,
                                     memory, bk_c, bv_c);

    // 1) xh = LN1(tgt)
    layernorm_kernel<<<NT_, 256>>>(tgt, g1, be1, xh);
    // 2) qkvh = RoPE(xh @ W_qkv + b)
    gemm_qkv<<<dim3(3 * Dd_ / 128, NT_ / 128), 128, GA_SMEM>>>(
        xh, wTh + WT_QKV, b_qkv, qkvh, rope_cos, rope_sin, 3 * Dd_, Dd_);
    // 3) causal self-attention (paired q-tiles) -> sah
    flash_attn_h<<<dim3(Ss_ / 128, Bb_ * Hh_), 128, FAH_SMEM>>>(qkvh, sah);
    // 4) tgtb = tgt + sah @ W_o + b_o
    gemm_mma<<<dim3(Dd_ / 128, NT_ / 128), 128, GA_SMEM>>>(
        sah, wTh + WT_O, b_o, tgt, tgtb, nullptr, Dd_, Dd_, 0);
    // 5) xh = LN2(tgtb)
    layernorm_kernel<<<NT_, 256>>>(tgtb, g2, be2, xh);
    // 6+7) merged: qc = xh @ Wq_c (fp16) AND kvc = memh @ [Wk|Wv] (fp32)
    gemm_qckv<<<272, 128, GA_SMEM>>>(
        xh, wTh + WT_QC, bq_c, qkvh,
        memh, wTh + WT_KC, b2c, kvc, Dd_);
    // 8) cross-attention -> sah
    cross_attn_kernel<<<dim3(Ss_, Bb_ * Hh_), 64>>>(qkvh, kvc, sah);
    // 9) tgtb += sah @ W_co + b_co
    gemm_mma<<<dim3(Dd_ / 128, NT_ / 128), 128, GA_SMEM>>>(
        sah, wTh + WT_CO, b_co, tgtb, tgtb, nullptr, Dd_, Dd_, 0);
    // 10) xh = LN3(tgtb)
    layernorm_kernel<<<NT_, 256>>>(tgtb, g3, be3, xh);
    // 11) ffnh = gelu(xh @ W1 + b1)
    gemm_mma<<<dim3(FF_ / 128, NT_ / 128), 128, GA_SMEM>>>(
        xh, wTh + WT_W1, b1, nullptr, nullptr, ffnh, FF_, Dd_, 1);
    // 12) out = tgtb + ffnh @ W2 + b2
    gemm_mma<<<dim3(Dd_ / 128, NT_ / 128), 128, GA_SMEM>>>(
        ffnh, wTh + WT_W2, b2, tgtb, out, nullptr, Dd_, FF_, 0);
}